// round 11
// baseline (speedup 1.0000x reference)
#include <cuda_runtime.h>
#include <cuda_bf16.h>
#include <cstdint>

#define Bv 8
#define Av 1024
#define NNv 64
#define Gv 25
#define Fv 128
#define Lv 3
#define NBT 4096            // tiles: 2 atoms / 128 edges each
#define EDGE_GRID 456

#define WIDTHc (5.0f/24.0f)
#define COEFFc (-0.5f/(WIDTHc*WIDTHc))
#define LN2c 0.6931471805599453f

// ---- dynamic smem offsets (bytes) for edge kernel (128-thr CTA, 3 CTA/SM) ----
#define OFF_YT   0          // bf16 [128 e][136]  stride 272B  (34816 B)
#define OFF_FW2T 34816      // bf16 [128 f][144]  quad-packed  (36864 B)
#define OFF_VSM  71680      // f32 [4][128] (2048 B)
#define SMEM_EDGE 73728

typedef unsigned long long ull;

// ---------------- scratch ----------------
__device__ __nv_bfloat16 g_y[Bv*Av*Fv];
__device__ float g_v[Bv*Av*Fv];
__device__ float g_r[Bv*Av*NNv];
__device__ uint2 g_b1pack[Lv][1024];   // GEMM1 B-fragments, fb1 folded at k=25

// ---------------- helpers ----------------
__device__ __forceinline__ float ssp(float x) {
    float u = __expf(-fabsf(x));
    float p = u*(0.99949556f + u*(-0.49190896f + u*(0.28947478f
              + u*(-0.13606275f + u*0.03215845f))));
    return fmaxf(x, 0.0f) + p - LN2c;
}
__device__ __forceinline__ uint32_t s2u(const void* p) {
    uint32_t a;
    asm("{ .reg .u64 t; cvta.to.shared.u64 t, %1; cvt.u32.u64 %0, t; }" : "=r"(a) : "l"(p));
    return a;
}
__device__ __forceinline__ uint32_t bf16pk(float lo, float hi) {
    uint32_t r;
    asm("cvt.rn.bf16x2.f32 %0, %1, %2;" : "=r"(r) : "f"(hi), "f"(lo));
    return r;
}
__device__ __forceinline__ float2 bf2f(uint32_t p) {
    float2 r;
    r.x = __uint_as_float(p << 16);
    r.y = __uint_as_float(p & 0xffff0000u);
    return r;
}
__device__ __forceinline__ void mma_bf16(float* d, const uint32_t* a, const uint32_t* b) {
    asm volatile(
        "mma.sync.aligned.m16n8k16.row.col.f32.bf16.bf16.f32 "
        "{%0,%1,%2,%3}, {%4,%5,%6,%7}, {%8,%9}, {%0,%1,%2,%3};"
        : "+f"(d[0]), "+f"(d[1]), "+f"(d[2]), "+f"(d[3])
        : "r"(a[0]), "r"(a[1]), "r"(a[2]), "r"(a[3]), "r"(b[0]), "r"(b[1]));
}
__device__ __forceinline__ void cp16(uint32_t dst, const void* src) {
    asm volatile("cp.async.ca.shared.global [%0], [%1], 16;" :: "r"(dst), "l"(src) : "memory");
}
__device__ __forceinline__ ull fma2(ull a, ull b, ull c) {
    ull d;
    asm("fma.rn.f32x2 %0, %1, %2, %3;" : "=l"(d) : "l"(a), "l"(b), "l"(c));
    return d;
}
__device__ __forceinline__ ull pack2(float lo, float hi) {
    ull d;
    asm("mov.b64 %0, {%1, %2};" : "=l"(d) : "f"(lo), "f"(hi));
    return d;
}
__device__ __forceinline__ float hsum2(ull v) {
    float lo, hi;
    asm("mov.b64 {%0, %1}, %2;" : "=f"(lo), "=f"(hi) : "l"(v));
    return lo + hi;
}
// packed ssp pair -> bf16x2: ((softplus(x0)-ln2)*m, (softplus(x1)-ln2)*m)
__device__ __forceinline__ uint32_t ssp2(float x0, float x1, ull Mv, ull MLv) {
    float u0 = __expf(-fabsf(x0));
    float u1 = __expf(-fabsf(x1));
    ull U = pack2(u0, u1);
    ull tt = fma2(U, pack2(0.03215845f, 0.03215845f), pack2(-0.13606275f, -0.13606275f));
    tt = fma2(U, tt, pack2(0.28947478f, 0.28947478f));
    tt = fma2(U, tt, pack2(-0.49190896f, -0.49190896f));
    tt = fma2(U, tt, pack2(0.99949556f, 0.99949556f));
    ull B = pack2(fmaxf(x0, 0.0f), fmaxf(x1, 0.0f));
    ull R = fma2(U, tt, B);
    R = fma2(R, Mv, MLv);
    float lo, hi;
    asm("mov.b64 {%0, %1}, %2;" : "=f"(lo), "=f"(hi) : "l"(R));
    return bf16pk(lo, hi);
}
// gaussian basis value for (possibly padded) index k; k=Gv slot carries the
// folded bias column (value 1.0). k is compile-time after unrolling.
__device__ __forceinline__ float gval(float r, int k) {
    if (k < Gv) { float d = r - (float)k * WIDTHc; return __expf(COEFFc * d * d); }
    return (k == Gv) ? 1.0f : 0.0f;
}

// R-rows x 128x128 GEMM core: thread owns column f, rows [r0, r0+R).
template<int R>
__device__ __forceinline__ void gemm_block(const float* sbuf, const float* __restrict__ W,
                                           int f, int r0, float* out)
{
    ull acc[R];
    #pragma unroll
    for (int i = 0; i < R; ++i) acc[i] = 0ull;
    const ull* xs = (const ull*)sbuf;
    #pragma unroll 2
    for (int kp = 0; kp < 64; ++kp) {
        ull wp = pack2(__ldg(W + 2*kp*Fv + f), __ldg(W + (2*kp+1)*Fv + f));
        #pragma unroll
        for (int r = 0; r < R; ++r)
            acc[r] = fma2(xs[(r0 + r)*64 + kp], wp, acc[r]);
    }
    #pragma unroll
    for (int r = 0; r < R; ++r) out[r] = hsum2(acc[r]);
}

// ---------------- kernel P: pack fw1 (+fb1 at k=25) into mma B-fragments ----------------
__global__ void pack_fw1_kernel(const float* __restrict__ fw1, const float* __restrict__ fb1)
{
    const int l = blockIdx.x;
    const int idx = threadIdx.x;               // 0..1023
    const int s  = idx >> 9;
    const int n  = (idx >> 5) & 15;
    const int ln = idx & 31;
    const int q2 = ln & 3, r2 = ln >> 2;
    const int g  = 2*q2 + 16*s;
    const int fn = 8*n + r2;
    const float* W = fw1 + (size_t)l*Gv*Fv;
    const float* B = fb1 + (size_t)l*Fv;
    float v0 = (g   < Gv) ? W[(g  )*Fv + fn] : ((g   == Gv) ? B[fn] : 0.0f);
    float v1 = (g+1 < Gv) ? W[(g+1)*Fv + fn] : ((g+1 == Gv) ? B[fn] : 0.0f);
    float v2 = (g+8 < Gv) ? W[(g+8)*Fv + fn] : ((g+8 == Gv) ? B[fn] : 0.0f);
    float v3 = (g+9 < Gv) ? W[(g+9)*Fv + fn] : ((g+9 == Gv) ? B[fn] : 0.0f);
    g_b1pack[l][idx] = make_uint2(bf16pk(v0, v1), bf16pk(v2, v3));
}

// ---------------- kernel 0: embedding + distances + y0 GEMM ----------------
__global__ __launch_bounds__(256)
void init_y_kernel(const int* __restrict__ zA, const float* __restrict__ pos,
                   const float* __restrict__ cell, const float* __restrict__ off,
                   const int* __restrict__ nbr, const float* __restrict__ emb,
                   const float* __restrict__ W3, float* __restrict__ x)
{
    __shared__ float bufA[64*Fv];
    __shared__ int zs[64];
    const int t = threadIdx.x;
    const int f = t & 127, q = t >> 7;
    const int row0 = blockIdx.x * 64;
    const int r0 = q * 32;

    if (t < 64) zs[t] = zA[row0 + t];

    for (int i = t; i < 64*NNv; i += 256) {
        int atom = row0 + (i >> 6);
        int e = atom*NNv + (i & 63);
        int b = atom >> 10;
        int nb = nbr[e];
        const float* pi = pos + (size_t)atom*3;
        const float* pj = pos + (size_t)((b<<10) + nb)*3;
        const float* o  = off + (size_t)e*3;
        const float* c  = cell + b*9;
        float dx = pj[0]-pi[0] + o[0]*c[0] + o[1]*c[3] + o[2]*c[6];
        float dy = pj[1]-pi[1] + o[0]*c[1] + o[1]*c[4] + o[2]*c[7];
        float dz = pj[2]-pi[2] + o[0]*c[2] + o[1]*c[5] + o[2]*c[8];
        float d2 = dx*dx + dy*dy + dz*dz;
        g_r[e] = (d2 > 0.0f) ? sqrtf(d2) : 0.0f;
    }
    __syncthreads();

    #pragma unroll
    for (int r = 0; r < 32; ++r) {
        int row = r0 + r;
        float val = emb[(size_t)zs[row]*Fv + f];
        bufA[row*Fv + f] = val;
        x[(size_t)(row0 + row)*Fv + f] = val;
    }
    __syncthreads();

    float out[32];
    gemm_block<32>(bufA, W3, f, r0, out);
    #pragma unroll
    for (int r = 0; r < 32; ++r)
        g_y[(size_t)(row0 + r0 + r)*Fv + f] = __float2bfloat16(out[r]);
}

// ---------------- kernel 2: mma.sync fused filter-net + cfconv ----------------
// 128-thr CTA = 2 atoms; 3 CTAs/SM (smem 72 KB, regs ~140 natural).
// Mt-interleaved (A2 half-size), b1 fragments via gmem LDG (pre-packed,
// bias folded at k=25), quad-packed FW2T (1 LDS.64/mma), fb2 analytic.
__global__ __launch_bounds__(128, 3)
void edge_mma_kernel(int layer, const float* __restrict__ fw2,
                     const float* __restrict__ fb2,
                     const int* __restrict__ nbr, const float* __restrict__ msk)
{
    extern __shared__ __align__(16) char sm[];
    __nv_bfloat16* YT   = (__nv_bfloat16*)(sm + OFF_YT);     // [128][136]
    __nv_bfloat16* FW2T = (__nv_bfloat16*)(sm + OFF_FW2T);   // [128][144] quad-packed
    float* VSM = (float*)(sm + OFF_VSM);                     // [4][128]

    const int t    = threadIdx.x;
    const int w    = t >> 5;
    const int lane = t & 31;
    const int qr   = lane >> 2;   // 0..7
    const int qc   = lane & 3;    // 0..3
    const uint32_t yt_base = s2u(YT);
    const uint2* __restrict__ b1p = g_b1pack[layer];

    // ---- per-layer setup: fw2^T quad-packed ----
    {
        const int f = t;
        #pragma unroll 2
        for (int s = 0; s < 8; ++s)
            for (int q2 = 0; q2 < 4; ++q2)
                #pragma unroll
                for (int j = 0; j < 4; ++j) {
                    int k = 16*s + 2*q2 + (j >> 1)*8 + (j & 1);
                    FW2T[f*144 + s*16 + q2*4 + j] = __float2bfloat16(fw2[k*Fv + f]);
                }
    }
    __syncthreads();

    for (int bt = blockIdx.x; bt < NBT; bt += gridDim.x) {
        const int e0 = bt * 128;

        // ---- A: issue y-row stage (bf16) via cp.async; row t is warp-local ----
        {
            int nb = __ldg(nbr + e0 + t);
            int batch = (e0 + t) >> 16;
            const __nv_bfloat16* src = g_y + ((size_t)batch << 17) + (size_t)nb * Fv;
            uint32_t dst = yt_base + (uint32_t)t * 272u;
            #pragma unroll
            for (int j = 0; j < 16; ++j)
                cp16(dst + 16u*j, (const char*)src + 16*j);
            asm volatile("cp.async.commit_group;" ::: "memory");
        }

        // ---- B: per M-tile: GEMM1 -> GEMM2 -> epilogue (VSM accumulate) ----
        #pragma unroll
        for (int Mt = 0; Mt < 2; ++Mt) {
            const int rg = e0 + 32*w + 16*Mt + qr;
            const float rr0 = __ldg(g_r + rg);
            const float rr1 = __ldg(g_r + rg + 8);
            const float m0  = __ldg(msk + rg);
            const float m1  = __ldg(msk + rg + 8);
            const ull Mv0 = pack2(m0, m0), Mv1 = pack2(m1, m1);
            const ull ML0 = pack2(-LN2c*m0, -LN2c*m0), ML1 = pack2(-LN2c*m1, -LN2c*m1);

            // gaussians (+bias column at k=25) -> A fragments
            uint32_t Af[2][4];
            #pragma unroll
            for (int s = 0; s < 2; ++s) {
                const int g = 2*qc + 16*s;
                Af[s][0] = bf16pk(gval(rr0, g  ), gval(rr0, g+1));
                Af[s][1] = bf16pk(gval(rr1, g  ), gval(rr1, g+1));
                Af[s][2] = bf16pk(gval(rr0, g+8), gval(rr0, g+9));
                Af[s][3] = bf16pk(gval(rr1, g+8), gval(rr1, g+9));
            }

            // GEMM1 -> A2 (bias included via packed column; mask folded)
            uint32_t A2[8][4];
            #pragma unroll
            for (int s2 = 0; s2 < 8; ++s2) {
                #pragma unroll
                for (int nn = 0; nn < 2; ++nn) {
                    const int n = 2*s2 + nn;
                    float acc[4] = {0.0f, 0.0f, 0.0f, 0.0f};
                    uint2 u0 = __ldg(b1p + n*32 + lane);
                    uint2 u1 = __ldg(b1p + 512 + n*32 + lane);
                    mma_bf16(acc, Af[0], (const uint32_t*)&u0);
                    mma_bf16(acc, Af[1], (const uint32_t*)&u1);
                    A2[s2][2*nn    ] = ssp2(acc[0], acc[1], Mv0, ML0);
                    A2[s2][2*nn + 1] = ssp2(acc[2], acc[3], Mv1, ML1);
                }
            }

            // YT ready before first epilogue (warp-local rows only)
            if (Mt == 0) {
                asm volatile("cp.async.wait_group 0;" ::: "memory");
                __syncwarp();
            }

            // GEMM2 (K=128) + epilogue with analytic fb2
            const int rl = 32*w + 16*Mt + qr;
            #pragma unroll
            for (int ch = 0; ch < 4; ++ch) {
                float acc2[4][4];
                #pragma unroll
                for (int n = 0; n < 4; ++n)
                    #pragma unroll
                    for (int i = 0; i < 4; ++i) acc2[n][i] = 0.0f;

                #pragma unroll
                for (int s = 0; s < 8; ++s) {
                    #pragma unroll
                    for (int n = 0; n < 4; ++n) {
                        int fB = 32*ch + 8*n + qr;
                        uint2 bb = *(const uint2*)(FW2T + fB*144 + s*16 + qc*4);
                        mma_bf16(acc2[n], A2[s], (const uint32_t*)&bb);
                    }
                }

                float vp[8];
                #pragma unroll
                for (int i = 0; i < 8; ++i) vp[i] = 0.0f;
                #pragma unroll
                for (int n = 0; n < 4; ++n) {
                    int fc = 32*ch + 8*n + 2*qc;
                    uint32_t y0 = *(const uint32_t*)(YT + rl*136 + fc);
                    uint32_t y1 = *(const uint32_t*)(YT + (rl+8)*136 + fc);
                    float2 f0 = bf2f(y0);
                    float2 f1 = bf2f(y1);
                    float2 fb = __ldg((const float2*)(fb2 + fc));
                    float t0 = fmaf(m1, f1.x, m0*f0.x);
                    float t1 = fmaf(m1, f1.y, m0*f0.y);
                    vp[2*n]   = fmaf(acc2[n][0], f0.x,
                                fmaf(acc2[n][2], f1.x,
                                fmaf(fb.x, t0, vp[2*n])));
                    vp[2*n+1] = fmaf(acc2[n][1], f0.y,
                                fmaf(acc2[n][3], f1.y,
                                fmaf(fb.y, t1, vp[2*n+1])));
                }
                #pragma unroll
                for (int i = 0; i < 8; ++i) {
                    vp[i] += __shfl_xor_sync(0xffffffffu, vp[i], 4);
                    vp[i] += __shfl_xor_sync(0xffffffffu, vp[i], 8);
                    vp[i] += __shfl_xor_sync(0xffffffffu, vp[i], 16);
                }
                if (lane < 4) {
                    #pragma unroll
                    for (int n = 0; n < 4; ++n) {
                        int idx0 = w*128 + 32*ch + 8*n + 2*lane;
                        if (Mt == 0) {
                            VSM[idx0    ] = vp[2*n];
                            VSM[idx0 + 1] = vp[2*n+1];
                        } else {
                            VSM[idx0    ] += vp[2*n];
                            VSM[idx0 + 1] += vp[2*n+1];
                        }
                    }
                }
            }
        }

        // ---- C: combine across warps -> g_v; protect VSM reuse ----
        __syncthreads();
        #pragma unroll
        for (int a = 0; a < 2; ++a)
            g_v[(size_t)(2*bt + a)*Fv + t] =
                VSM[(2*a)*128 + t] + VSM[(2*a+1)*128 + t];
        __syncthreads();
    }
}

// ---------------- kernel 3: x += dense(ssp(f2out(v)))  [+ next-layer in2f] ----------------
template<int DO_Y>
__global__ __launch_bounds__(256)
void fused_post(const float* __restrict__ W1, const float* __restrict__ B1,
                const float* __restrict__ W2, const float* __restrict__ B2,
                const float* __restrict__ W3, float* __restrict__ x)
{
    extern __shared__ float fsm[];
    float* bufA = fsm;              // [16][128]
    float* bufB = fsm + 16*Fv;      // [16][128]
    const int t = threadIdx.x;
    const int f = t & 127, q = t >> 7;
    const int row0 = blockIdx.x * 16;
    const int r0 = q * 8;

    {   // load v tile
        const float4* src = (const float4*)(g_v + (size_t)row0 * Fv);
        float4* dst = (float4*)bufA;
        #pragma unroll
        for (int i = 0; i < 2; ++i) dst[t + 256*i] = src[t + 256*i];
    }
    __syncthreads();

    float out[8];
    gemm_block<8>(bufA, W1, f, r0, out);
    {
        float b = __ldg(B1 + f);
        #pragma unroll
        for (int r = 0; r < 8; ++r)
            bufB[(r0 + r)*Fv + f] = ssp(out[r] + b);
    }
    __syncthreads();

    gemm_block<8>(bufB, W2, f, r0, out);
    {
        float b = __ldg(B2 + f);
        #pragma unroll
        for (int r = 0; r < 8; ++r) {
            size_t gi = (size_t)(row0 + r0 + r)*Fv + f;
            float xn = x[gi] + out[r] + b;
            x[gi] = xn;
            if (DO_Y) bufA[(r0 + r)*Fv + f] = xn;
        }
    }
    if (DO_Y) {
        __syncthreads();
        gemm_block<8>(bufA, W3, f, r0, out);
        #pragma unroll
        for (int r = 0; r < 8; ++r)
            g_y[(size_t)(row0 + r0 + r)*Fv + f] = __float2bfloat16(out[r]);
    }
}

// ---------------- launcher ----------------
extern "C" void kernel_launch(void* const* d_in, const int* in_sizes, int n_in,
                              void* d_out, int out_size)
{
    const int*   zA   = (const int*)  d_in[0];
    const float* pos  = (const float*)d_in[1];
    const float* cell = (const float*)d_in[2];
    const float* off  = (const float*)d_in[3];
    const int*   nbr  = (const int*)  d_in[4];
    const float* msk  = (const float*)d_in[5];
    const float* emb  = (const float*)d_in[6];
    const float* fw1  = (const float*)d_in[7];
    const float* fb1  = (const float*)d_in[8];
    const float* fw2  = (const float*)d_in[9];
    const float* fb2  = (const float*)d_in[10];
    const float* i2f  = (const float*)d_in[11];
    const float* f2o  = (const float*)d_in[12];
    const float* f2ob = (const float*)d_in[13];
    const float* dw   = (const float*)d_in[14];
    const float* db   = (const float*)d_in[15];
    float* x = (float*)d_out;

    cudaFuncSetAttribute(edge_mma_kernel,
                         cudaFuncAttributeMaxDynamicSharedMemorySize, SMEM_EDGE);
    cudaFuncSetAttribute(fused_post<1>,
                         cudaFuncAttributeMaxDynamicSharedMemorySize, 16384);
    cudaFuncSetAttribute(fused_post<0>,
                         cudaFuncAttributeMaxDynamicSharedMemorySize, 16384);

    pack_fw1_kernel<<<Lv, 1024>>>(fw1, fb1);
    init_y_kernel<<<(Bv*Av)/64, 256>>>(zA, pos, cell, off, nbr, emb, i2f, x);
    for (int l = 0; l < Lv; ++l) {
        edge_mma_kernel<<<EDGE_GRID, 128, SMEM_EDGE>>>(
            l, fw2 + (size_t)l*Fv*Fv, fb2 + (size_t)l*Fv, nbr, msk);
        if (l < Lv - 1)
            fused_post<1><<<(Bv*Av)/16, 256, 16384>>>(
                f2o + (size_t)l*Fv*Fv, f2ob + (size_t)l*Fv,
                dw  + (size_t)l*Fv*Fv, db   + (size_t)l*Fv,
                i2f + (size_t)(l+1)*Fv*Fv, x);
        else
            fused_post<0><<<(Bv*Av)/16, 256, 16384>>>(
                f2o + (size_t)l*Fv*Fv, f2ob + (size_t)l*Fv,
                dw  + (size_t)l*Fv*Fv, db   + (size_t)l*Fv,
                (const float*)nullptr, x);
    }
}

// round 12
// speedup vs baseline: 1.0074x; 1.0074x over previous
#include <cuda_runtime.h>
#include <cuda_bf16.h>
#include <cstdint>

#define Bv 8
#define Av 1024
#define NNv 64
#define Gv 25
#define Fv 128
#define Lv 3
#define NBT 4096            // tiles: 2 atoms / 128 edges each
#define EDGE_GRID 456

#define WIDTHc (5.0f/24.0f)
#define COEFFc (-0.5f/(WIDTHc*WIDTHc))
#define LN2c 0.6931471805599453f

// ---- dynamic smem offsets (bytes) for edge kernel (128-thr CTA, 3 CTA/SM) ----
#define OFF_YT   0          // bf16 [128 e][136]  stride 272B  (34816 B)
#define OFF_FW2T 34816      // bf16 [128 f][144]  quad-packed  (36864 B)
#define OFF_VSM  71680      // f32 [4][128] (2048 B)
#define SMEM_EDGE 73728

typedef unsigned long long ull;

// ---------------- scratch ----------------
__device__ __nv_bfloat16 g_y[Bv*Av*Fv];
__device__ float g_v[Bv*Av*Fv];
__device__ float g_r[Bv*Av*NNv];
__device__ uint2 g_b1pack[Lv][1024];   // GEMM1 B-fragments, fb1 folded at k=25

// ---------------- helpers ----------------
__device__ __forceinline__ float ssp(float x) {
    float u = __expf(-fabsf(x));
    float p = u*(0.99949556f + u*(-0.49190896f + u*(0.28947478f
              + u*(-0.13606275f + u*0.03215845f))));
    return fmaxf(x, 0.0f) + p - LN2c;
}
__device__ __forceinline__ uint32_t s2u(const void* p) {
    uint32_t a;
    asm("{ .reg .u64 t; cvta.to.shared.u64 t, %1; cvt.u32.u64 %0, t; }" : "=r"(a) : "l"(p));
    return a;
}
__device__ __forceinline__ uint32_t bf16pk(float lo, float hi) {
    uint32_t r;
    asm("cvt.rn.bf16x2.f32 %0, %1, %2;" : "=r"(r) : "f"(hi), "f"(lo));
    return r;
}
__device__ __forceinline__ float2 bf2f(uint32_t p) {
    float2 r;
    r.x = __uint_as_float(p << 16);
    r.y = __uint_as_float(p & 0xffff0000u);
    return r;
}
__device__ __forceinline__ void mma_bf16(float* d, const uint32_t* a, const uint32_t* b) {
    asm volatile(
        "mma.sync.aligned.m16n8k16.row.col.f32.bf16.bf16.f32 "
        "{%0,%1,%2,%3}, {%4,%5,%6,%7}, {%8,%9}, {%0,%1,%2,%3};"
        : "+f"(d[0]), "+f"(d[1]), "+f"(d[2]), "+f"(d[3])
        : "r"(a[0]), "r"(a[1]), "r"(a[2]), "r"(a[3]), "r"(b[0]), "r"(b[1]));
}
__device__ __forceinline__ void cp16(uint32_t dst, const void* src) {
    asm volatile("cp.async.ca.shared.global [%0], [%1], 16;" :: "r"(dst), "l"(src) : "memory");
}
__device__ __forceinline__ ull fma2(ull a, ull b, ull c) {
    ull d;
    asm("fma.rn.f32x2 %0, %1, %2, %3;" : "=l"(d) : "l"(a), "l"(b), "l"(c));
    return d;
}
__device__ __forceinline__ ull pack2(float lo, float hi) {
    ull d;
    asm("mov.b64 %0, {%1, %2};" : "=l"(d) : "f"(lo), "f"(hi));
    return d;
}
__device__ __forceinline__ float hsum2(ull v) {
    float lo, hi;
    asm("mov.b64 {%0, %1}, %2;" : "=f"(lo), "=f"(hi) : "l"(v));
    return lo + hi;
}
// packed ssp pair -> bf16x2: ((softplus(x0)-ln2)*m, (softplus(x1)-ln2)*m)
__device__ __forceinline__ uint32_t ssp2(float x0, float x1, ull Mv, ull MLv) {
    float u0 = __expf(-fabsf(x0));
    float u1 = __expf(-fabsf(x1));
    ull U = pack2(u0, u1);
    ull tt = fma2(U, pack2(0.03215845f, 0.03215845f), pack2(-0.13606275f, -0.13606275f));
    tt = fma2(U, tt, pack2(0.28947478f, 0.28947478f));
    tt = fma2(U, tt, pack2(-0.49190896f, -0.49190896f));
    tt = fma2(U, tt, pack2(0.99949556f, 0.99949556f));
    ull B = pack2(fmaxf(x0, 0.0f), fmaxf(x1, 0.0f));
    ull R = fma2(U, tt, B);
    R = fma2(R, Mv, MLv);
    float lo, hi;
    asm("mov.b64 {%0, %1}, %2;" : "=f"(lo), "=f"(hi) : "l"(R));
    return bf16pk(lo, hi);
}
// gaussian basis value; k=Gv slot is the folded bias column (1.0)
__device__ __forceinline__ float gval(float r, int k) {
    if (k < Gv) { float d = r - (float)k * WIDTHc; return __expf(COEFFc * d * d); }
    return (k == Gv) ? 1.0f : 0.0f;
}

// R-rows x 128x128 GEMM core: thread owns column f, rows [r0, r0+R).
template<int R>
__device__ __forceinline__ void gemm_block(const float* sbuf, const float* __restrict__ W,
                                           int f, int r0, float* out)
{
    ull acc[R];
    #pragma unroll
    for (int i = 0; i < R; ++i) acc[i] = 0ull;
    const ull* xs = (const ull*)sbuf;
    #pragma unroll 2
    for (int kp = 0; kp < 64; ++kp) {
        ull wp = pack2(__ldg(W + 2*kp*Fv + f), __ldg(W + (2*kp+1)*Fv + f));
        #pragma unroll
        for (int r = 0; r < R; ++r)
            acc[r] = fma2(xs[(r0 + r)*64 + kp], wp, acc[r]);
    }
    #pragma unroll
    for (int r = 0; r < R; ++r) out[r] = hsum2(acc[r]);
}

// ---------------- kernel P: pack fw1 (+fb1 at k=25) into mma B-fragments ----------------
__global__ void pack_fw1_kernel(const float* __restrict__ fw1, const float* __restrict__ fb1)
{
    const int l = blockIdx.x;
    const int idx = threadIdx.x;               // 0..1023
    const int s  = idx >> 9;
    const int n  = (idx >> 5) & 15;
    const int ln = idx & 31;
    const int q2 = ln & 3, r2 = ln >> 2;
    const int g  = 2*q2 + 16*s;
    const int fn = 8*n + r2;
    const float* W = fw1 + (size_t)l*Gv*Fv;
    const float* B = fb1 + (size_t)l*Fv;
    float v0 = (g   < Gv) ? W[(g  )*Fv + fn] : ((g   == Gv) ? B[fn] : 0.0f);
    float v1 = (g+1 < Gv) ? W[(g+1)*Fv + fn] : ((g+1 == Gv) ? B[fn] : 0.0f);
    float v2 = (g+8 < Gv) ? W[(g+8)*Fv + fn] : ((g+8 == Gv) ? B[fn] : 0.0f);
    float v3 = (g+9 < Gv) ? W[(g+9)*Fv + fn] : ((g+9 == Gv) ? B[fn] : 0.0f);
    g_b1pack[l][idx] = make_uint2(bf16pk(v0, v1), bf16pk(v2, v3));
}

// ---------------- kernel 0: embedding + distances + y0 GEMM ----------------
__global__ __launch_bounds__(256)
void init_y_kernel(const int* __restrict__ zA, const float* __restrict__ pos,
                   const float* __restrict__ cell, const float* __restrict__ off,
                   const int* __restrict__ nbr, const float* __restrict__ emb,
                   const float* __restrict__ W3, float* __restrict__ x)
{
    __shared__ float bufA[64*Fv];
    __shared__ int zs[64];
    const int t = threadIdx.x;
    const int f = t & 127, q = t >> 7;
    const int row0 = blockIdx.x * 64;
    const int r0 = q * 32;

    if (t < 64) zs[t] = zA[row0 + t];

    for (int i = t; i < 64*NNv; i += 256) {
        int atom = row0 + (i >> 6);
        int e = atom*NNv + (i & 63);
        int b = atom >> 10;
        int nb = nbr[e];
        const float* pi = pos + (size_t)atom*3;
        const float* pj = pos + (size_t)((b<<10) + nb)*3;
        const float* o  = off + (size_t)e*3;
        const float* c  = cell + b*9;
        float dx = pj[0]-pi[0] + o[0]*c[0] + o[1]*c[3] + o[2]*c[6];
        float dy = pj[1]-pi[1] + o[0]*c[1] + o[1]*c[4] + o[2]*c[7];
        float dz = pj[2]-pi[2] + o[0]*c[2] + o[1]*c[5] + o[2]*c[8];
        float d2 = dx*dx + dy*dy + dz*dz;
        g_r[e] = (d2 > 0.0f) ? sqrtf(d2) : 0.0f;
    }
    __syncthreads();

    #pragma unroll
    for (int r = 0; r < 32; ++r) {
        int row = r0 + r;
        float val = emb[(size_t)zs[row]*Fv + f];
        bufA[row*Fv + f] = val;
        x[(size_t)(row0 + row)*Fv + f] = val;
    }
    __syncthreads();

    float out[32];
    gemm_block<32>(bufA, W3, f, r0, out);
    #pragma unroll
    for (int r = 0; r < 32; ++r)
        g_y[(size_t)(row0 + r0 + r)*Fv + f] = __float2bfloat16(out[r]);
}

// ---------------- kernel 2: mma.sync fused filter-net + cfconv ----------------
// 128-thr CTA = 2 atoms; 3 CTAs/SM. Mt-interleaved, b1 fragments via gmem
// LDG (pre-packed, bias folded at k=25), quad-packed FW2T, fb2 analytic.
__global__ __launch_bounds__(128, 3)
void edge_mma_kernel(int layer, const float* __restrict__ fw2,
                     const float* __restrict__ fb2,
                     const int* __restrict__ nbr, const float* __restrict__ msk)
{
    extern __shared__ __align__(16) char sm[];
    __nv_bfloat16* YT   = (__nv_bfloat16*)(sm + OFF_YT);     // [128][136]
    __nv_bfloat16* FW2T = (__nv_bfloat16*)(sm + OFF_FW2T);   // [128][144] quad-packed
    float* VSM = (float*)(sm + OFF_VSM);                     // [4][128]

    const int t    = threadIdx.x;
    const int w    = t >> 5;
    const int lane = t & 31;
    const int qr   = lane >> 2;   // 0..7
    const int qc   = lane & 3;    // 0..3
    const uint32_t yt_base = s2u(YT);
    const uint2* __restrict__ b1p = g_b1pack[layer];

    // ---- per-layer setup: fw2^T quad-packed ----
    {
        const int f = t;
        #pragma unroll 2
        for (int s = 0; s < 8; ++s)
            for (int q2 = 0; q2 < 4; ++q2)
                #pragma unroll
                for (int j = 0; j < 4; ++j) {
                    int k = 16*s + 2*q2 + (j >> 1)*8 + (j & 1);
                    FW2T[f*144 + s*16 + q2*4 + j] = __float2bfloat16(fw2[k*Fv + f]);
                }
    }
    __syncthreads();

    for (int bt = blockIdx.x; bt < NBT; bt += gridDim.x) {
        const int e0 = bt * 128;

        // ---- A: issue y-row stage (bf16) via cp.async; row t is warp-local ----
        {
            int nb = __ldg(nbr + e0 + t);
            int batch = (e0 + t) >> 16;
            const __nv_bfloat16* src = g_y + ((size_t)batch << 17) + (size_t)nb * Fv;
            uint32_t dst = yt_base + (uint32_t)t * 272u;
            #pragma unroll
            for (int j = 0; j < 16; ++j)
                cp16(dst + 16u*j, (const char*)src + 16*j);
            asm volatile("cp.async.commit_group;" ::: "memory");
        }

        // ---- B: per M-tile: GEMM1 -> GEMM2 -> epilogue (VSM accumulate) ----
        #pragma unroll
        for (int Mt = 0; Mt < 2; ++Mt) {
            const int rg = e0 + 32*w + 16*Mt + qr;
            const float rr0 = __ldg(g_r + rg);
            const float rr1 = __ldg(g_r + rg + 8);
            const float m0  = __ldg(msk + rg);
            const float m1  = __ldg(msk + rg + 8);
            const ull Mv0 = pack2(m0, m0), Mv1 = pack2(m1, m1);
            const ull ML0 = pack2(-LN2c*m0, -LN2c*m0), ML1 = pack2(-LN2c*m1, -LN2c*m1);

            // gaussians (+bias column at k=25) -> A fragments
            uint32_t Af[2][4];
            #pragma unroll
            for (int s = 0; s < 2; ++s) {
                const int g = 2*qc + 16*s;
                Af[s][0] = bf16pk(gval(rr0, g  ), gval(rr0, g+1));
                Af[s][1] = bf16pk(gval(rr1, g  ), gval(rr1, g+1));
                Af[s][2] = bf16pk(gval(rr0, g+8), gval(rr0, g+9));
                Af[s][3] = bf16pk(gval(rr1, g+8), gval(rr1, g+9));
            }

            // GEMM1 -> A2 (bias via packed column; mask folded in ssp2)
            uint32_t A2[8][4];
            #pragma unroll
            for (int s2 = 0; s2 < 8; ++s2) {
                #pragma unroll
                for (int nn = 0; nn < 2; ++nn) {
                    const int n = 2*s2 + nn;
                    float acc[4] = {0.0f, 0.0f, 0.0f, 0.0f};
                    uint2 u0 = __ldg(b1p + n*32 + lane);
                    uint2 u1 = __ldg(b1p + 512 + n*32 + lane);
                    mma_bf16(acc, Af[0], (const uint32_t*)&u0);
                    mma_bf16(acc, Af[1], (const uint32_t*)&u1);
                    A2[s2][2*nn    ] = ssp2(acc[0], acc[1], Mv0, ML0);
                    A2[s2][2*nn + 1] = ssp2(acc[2], acc[3], Mv1, ML1);
                }
            }

            // YT ready before first epilogue (warp-local rows only)
            if (Mt == 0) {
                asm volatile("cp.async.wait_group 0;" ::: "memory");
                __syncwarp();
            }

            // GEMM2 (K=128) + epilogue with analytic fb2
            const int rl = 32*w + 16*Mt + qr;
            #pragma unroll
            for (int ch = 0; ch < 4; ++ch) {
                float acc2[4][4];
                #pragma unroll
                for (int n = 0; n < 4; ++n)
                    #pragma unroll
                    for (int i = 0; i < 4; ++i) acc2[n][i] = 0.0f;

                #pragma unroll
                for (int s = 0; s < 8; ++s) {
                    #pragma unroll
                    for (int n = 0; n < 4; ++n) {
                        int fB = 32*ch + 8*n + qr;
                        uint2 bb = *(const uint2*)(FW2T + fB*144 + s*16 + qc*4);
                        mma_bf16(acc2[n], A2[s], (const uint32_t*)&bb);
                    }
                }

                float vp[8];
                #pragma unroll
                for (int i = 0; i < 8; ++i) vp[i] = 0.0f;
                #pragma unroll
                for (int n = 0; n < 4; ++n) {
                    int fc = 32*ch + 8*n + 2*qc;
                    uint32_t y0 = *(const uint32_t*)(YT + rl*136 + fc);
                    uint32_t y1 = *(const uint32_t*)(YT + (rl+8)*136 + fc);
                    float2 f0 = bf2f(y0);
                    float2 f1 = bf2f(y1);
                    float2 fb = __ldg((const float2*)(fb2 + fc));
                    float t0 = fmaf(m1, f1.x, m0*f0.x);
                    float t1 = fmaf(m1, f1.y, m0*f0.y);
                    vp[2*n]   = fmaf(acc2[n][0], f0.x,
                                fmaf(acc2[n][2], f1.x,
                                fmaf(fb.x, t0, vp[2*n])));
                    vp[2*n+1] = fmaf(acc2[n][1], f0.y,
                                fmaf(acc2[n][3], f1.y,
                                fmaf(fb.y, t1, vp[2*n+1])));
                }
                #pragma unroll
                for (int i = 0; i < 8; ++i) {
                    vp[i] += __shfl_xor_sync(0xffffffffu, vp[i], 4);
                    vp[i] += __shfl_xor_sync(0xffffffffu, vp[i], 8);
                    vp[i] += __shfl_xor_sync(0xffffffffu, vp[i], 16);
                }
                if (lane < 4) {
                    #pragma unroll
                    for (int n = 0; n < 4; ++n) {
                        int idx0 = w*128 + 32*ch + 8*n + 2*lane;
                        if (Mt == 0) {
                            VSM[idx0    ] = vp[2*n];
                            VSM[idx0 + 1] = vp[2*n+1];
                        } else {
                            VSM[idx0    ] += vp[2*n];
                            VSM[idx0 + 1] += vp[2*n+1];
                        }
                    }
                }
            }
        }

        // ---- C: combine across warps -> g_v; protect VSM reuse ----
        __syncthreads();
        #pragma unroll
        for (int a = 0; a < 2; ++a)
            g_v[(size_t)(2*bt + a)*Fv + t] =
                VSM[(2*a)*128 + t] + VSM[(2*a+1)*128 + t];
        __syncthreads();
    }
}

// ---------------- kernel 3: x += dense(ssp(f2out(v)))  [+ next-layer in2f] ----------------
// 32-row tiles (R10 configuration).
template<int DO_Y>
__global__ __launch_bounds__(256)
void fused_post(const float* __restrict__ W1, const float* __restrict__ B1,
                const float* __restrict__ W2, const float* __restrict__ B2,
                const float* __restrict__ W3, float* __restrict__ x)
{
    extern __shared__ float fsm[];
    float* bufA = fsm;              // [32][128]
    float* bufB = fsm + 32*Fv;      // [32][128]
    const int t = threadIdx.x;
    const int f = t & 127, q = t >> 7;
    const int row0 = blockIdx.x * 32;
    const int r0 = q * 16;

    {   // load v tile
        const float4* src = (const float4*)(g_v + (size_t)row0 * Fv);
        float4* dst = (float4*)bufA;
        #pragma unroll
        for (int i = 0; i < 4; ++i) dst[t + 256*i] = src[t + 256*i];
    }
    __syncthreads();

    float out[16];
    gemm_block<16>(bufA, W1, f, r0, out);
    {
        float b = __ldg(B1 + f);
        #pragma unroll
        for (int r = 0; r < 16; ++r)
            bufB[(r0 + r)*Fv + f] = ssp(out[r] + b);
    }
    __syncthreads();

    gemm_block<16>(bufB, W2, f, r0, out);
    {
        float b = __ldg(B2 + f);
        #pragma unroll
        for (int r = 0; r < 16; ++r) {
            size_t gi = (size_t)(row0 + r0 + r)*Fv + f;
            float xn = x[gi] + out[r] + b;
            x[gi] = xn;
            if (DO_Y) bufA[(r0 + r)*Fv + f] = xn;
        }
    }
    if (DO_Y) {
        __syncthreads();
        gemm_block<16>(bufA, W3, f, r0, out);
        #pragma unroll
        for (int r = 0; r < 16; ++r)
            g_y[(size_t)(row0 + r0 + r)*Fv + f] = __float2bfloat16(out[r]);
    }
}

// ---------------- launcher ----------------
extern "C" void kernel_launch(void* const* d_in, const int* in_sizes, int n_in,
                              void* d_out, int out_size)
{
    const int*   zA   = (const int*)  d_in[0];
    const float* pos  = (const float*)d_in[1];
    const float* cell = (const float*)d_in[2];
    const float* off  = (const float*)d_in[3];
    const int*   nbr  = (const int*)  d_in[4];
    const float* msk  = (const float*)d_in[5];
    const float* emb  = (const float*)d_in[6];
    const float* fw1  = (const float*)d_in[7];
    const float* fb1  = (const float*)d_in[8];
    const float* fw2  = (const float*)d_in[9];
    const float* fb2  = (const float*)d_in[10];
    const float* i2f  = (const float*)d_in[11];
    const float* f2o  = (const float*)d_in[12];
    const float* f2ob = (const float*)d_in[13];
    const float* dw   = (const float*)d_in[14];
    const float* db   = (const float*)d_in[15];
    float* x = (float*)d_out;

    cudaFuncSetAttribute(edge_mma_kernel,
                         cudaFuncAttributeMaxDynamicSharedMemorySize, SMEM_EDGE);
    cudaFuncSetAttribute(fused_post<1>,
                         cudaFuncAttributeMaxDynamicSharedMemorySize, 32768);
    cudaFuncSetAttribute(fused_post<0>,
                         cudaFuncAttributeMaxDynamicSharedMemorySize, 32768);

    pack_fw1_kernel<<<Lv, 1024>>>(fw1, fb1);
    init_y_kernel<<<(Bv*Av)/64, 256>>>(zA, pos, cell, off, nbr, emb, i2f, x);
    for (int l = 0; l < Lv; ++l) {
        edge_mma_kernel<<<EDGE_GRID, 128, SMEM_EDGE>>>(
            l, fw2 + (size_t)l*Fv*Fv, fb2 + (size_t)l*Fv, nbr, msk);
        if (l < Lv - 1)
            fused_post<1><<<(Bv*Av)/32, 256, 32768>>>(
                f2o + (size_t)l*Fv*Fv, f2ob + (size_t)l*Fv,
                dw  + (size_t)l*Fv*Fv, db   + (size_t)l*Fv,
                i2f + (size_t)(l+1)*Fv*Fv, x);
        else
            fused_post<0><<<(Bv*Av)/32, 256, 32768>>>(
                f2o + (size_t)l*Fv*Fv, f2ob + (size_t)l*Fv,
                dw  + (size_t)l*Fv*Fv, db   + (size_t)l*Fv,
                (const float*)nullptr, x);
    }
}

// round 13
// speedup vs baseline: 1.0645x; 1.0567x over previous
#include <cuda_runtime.h>
#include <cuda_bf16.h>
#include <cstdint>

#define Bv 8
#define Av 1024
#define NNv 64
#define Gv 25
#define Fv 128
#define Lv 3
#define NBT 4096            // tiles: 2 atoms / 128 edges each
#define NSM 152

#define WIDTHc (5.0f/24.0f)
#define COEFFc (-0.5f/(WIDTHc*WIDTHc))
#define LN2c 0.6931471805599453f

// ---- dynamic smem offsets (bytes) for edge kernel (128-thr CTA) ----
#define OFF_YT   0          // bf16 [128 e][136]  stride 272B  (34816 B)
#define OFF_FW2T 34816      // bf16 [128 f][144]  quad-packed  (36864 B)
#define OFF_VSM  71680      // f32 2 x [4][128] ping-pong (4096 B)
#define SMEM_EDGE 75776

typedef unsigned long long ull;

// ---------------- scratch ----------------
__device__ __nv_bfloat16 g_y[Bv*Av*Fv];
__device__ float g_v[Bv*Av*Fv];
__device__ float g_r[Bv*Av*NNv];
__device__ uint2 g_b1pack[Lv][1024];   // GEMM1 B-fragments, fb1 folded at k=25

// ---------------- helpers ----------------
__device__ __forceinline__ float ssp(float x) {
    float u = __expf(-fabsf(x));
    float p = u*(0.99949556f + u*(-0.49190896f + u*(0.28947478f
              + u*(-0.13606275f + u*0.03215845f))));
    return fmaxf(x, 0.0f) + p - LN2c;
}
__device__ __forceinline__ uint32_t s2u(const void* p) {
    uint32_t a;
    asm("{ .reg .u64 t; cvta.to.shared.u64 t, %1; cvt.u32.u64 %0, t; }" : "=r"(a) : "l"(p));
    return a;
}
__device__ __forceinline__ uint32_t bf16pk(float lo, float hi) {
    uint32_t r;
    asm("cvt.rn.bf16x2.f32 %0, %1, %2;" : "=r"(r) : "f"(hi), "f"(lo));
    return r;
}
__device__ __forceinline__ float2 bf2f(uint32_t p) {
    float2 r;
    r.x = __uint_as_float(p << 16);
    r.y = __uint_as_float(p & 0xffff0000u);
    return r;
}
__device__ __forceinline__ void mma_bf16(float* d, const uint32_t* a, const uint32_t* b) {
    asm volatile(
        "mma.sync.aligned.m16n8k16.row.col.f32.bf16.bf16.f32 "
        "{%0,%1,%2,%3}, {%4,%5,%6,%7}, {%8,%9}, {%0,%1,%2,%3};"
        : "+f"(d[0]), "+f"(d[1]), "+f"(d[2]), "+f"(d[3])
        : "r"(a[0]), "r"(a[1]), "r"(a[2]), "r"(a[3]), "r"(b[0]), "r"(b[1]));
}
__device__ __forceinline__ void cp16(uint32_t dst, const void* src) {
    asm volatile("cp.async.ca.shared.global [%0], [%1], 16;" :: "r"(dst), "l"(src) : "memory");
}
__device__ __forceinline__ ull fma2(ull a, ull b, ull c) {
    ull d;
    asm("fma.rn.f32x2 %0, %1, %2, %3;" : "=l"(d) : "l"(a), "l"(b), "l"(c));
    return d;
}
__device__ __forceinline__ ull pack2(float lo, float hi) {
    ull d;
    asm("mov.b64 %0, {%1, %2};" : "=l"(d) : "f"(lo), "f"(hi));
    return d;
}
__device__ __forceinline__ float hsum2(ull v) {
    float lo, hi;
    asm("mov.b64 {%0, %1}, %2;" : "=f"(lo), "=f"(hi) : "l"(v));
    return lo + hi;
}
// packed ssp pair -> bf16x2: ((softplus(x0)-ln2)*m, (softplus(x1)-ln2)*m)
__device__ __forceinline__ uint32_t ssp2(float x0, float x1, ull Mv, ull MLv) {
    float u0 = __expf(-fabsf(x0));
    float u1 = __expf(-fabsf(x1));
    ull U = pack2(u0, u1);
    ull tt = fma2(U, pack2(0.03215845f, 0.03215845f), pack2(-0.13606275f, -0.13606275f));
    tt = fma2(U, tt, pack2(0.28947478f, 0.28947478f));
    tt = fma2(U, tt, pack2(-0.49190896f, -0.49190896f));
    tt = fma2(U, tt, pack2(0.99949556f, 0.99949556f));
    ull B = pack2(fmaxf(x0, 0.0f), fmaxf(x1, 0.0f));
    ull R = fma2(U, tt, B);
    R = fma2(R, Mv, MLv);
    float lo, hi;
    asm("mov.b64 {%0, %1}, %2;" : "=f"(lo), "=f"(hi) : "l"(R));
    return bf16pk(lo, hi);
}
// gaussian basis value; k=Gv slot is the folded bias column (1.0)
__device__ __forceinline__ float gval(float r, int k) {
    if (k < Gv) { float d = r - (float)k * WIDTHc; return __expf(COEFFc * d * d); }
    return (k == Gv) ? 1.0f : 0.0f;
}

// R-rows x 128x128 GEMM core: thread owns column f, rows [r0, r0+R).
template<int R>
__device__ __forceinline__ void gemm_block(const float* sbuf, const float* __restrict__ W,
                                           int f, int r0, float* out)
{
    ull acc[R];
    #pragma unroll
    for (int i = 0; i < R; ++i) acc[i] = 0ull;
    const ull* xs = (const ull*)sbuf;
    #pragma unroll 2
    for (int kp = 0; kp < 64; ++kp) {
        ull wp = pack2(__ldg(W + 2*kp*Fv + f), __ldg(W + (2*kp+1)*Fv + f));
        #pragma unroll
        for (int r = 0; r < R; ++r)
            acc[r] = fma2(xs[(r0 + r)*64 + kp], wp, acc[r]);
    }
    #pragma unroll
    for (int r = 0; r < R; ++r) out[r] = hsum2(acc[r]);
}

// ---------------- kernel P: pack fw1 (+fb1 at k=25) into mma B-fragments ----------------
__global__ void pack_fw1_kernel(const float* __restrict__ fw1, const float* __restrict__ fb1)
{
    const int l = blockIdx.x;
    const int idx = threadIdx.x;               // 0..1023
    const int s  = idx >> 9;
    const int n  = (idx >> 5) & 15;
    const int ln = idx & 31;
    const int q2 = ln & 3, r2 = ln >> 2;
    const int g  = 2*q2 + 16*s;
    const int fn = 8*n + r2;
    const float* W = fw1 + (size_t)l*Gv*Fv;
    const float* B = fb1 + (size_t)l*Fv;
    float v0 = (g   < Gv) ? W[(g  )*Fv + fn] : ((g   == Gv) ? B[fn] : 0.0f);
    float v1 = (g+1 < Gv) ? W[(g+1)*Fv + fn] : ((g+1 == Gv) ? B[fn] : 0.0f);
    float v2 = (g+8 < Gv) ? W[(g+8)*Fv + fn] : ((g+8 == Gv) ? B[fn] : 0.0f);
    float v3 = (g+9 < Gv) ? W[(g+9)*Fv + fn] : ((g+9 == Gv) ? B[fn] : 0.0f);
    g_b1pack[l][idx] = make_uint2(bf16pk(v0, v1), bf16pk(v2, v3));
}

// ---------------- kernel 0: embedding + distances + y0 GEMM ----------------
__global__ __launch_bounds__(256)
void init_y_kernel(const int* __restrict__ zA, const float* __restrict__ pos,
                   const float* __restrict__ cell, const float* __restrict__ off,
                   const int* __restrict__ nbr, const float* __restrict__ emb,
                   const float* __restrict__ W3, float* __restrict__ x)
{
    __shared__ float bufA[64*Fv];
    __shared__ int zs[64];
    const int t = threadIdx.x;
    const int f = t & 127, q = t >> 7;
    const int row0 = blockIdx.x * 64;
    const int r0 = q * 32;

    if (t < 64) zs[t] = zA[row0 + t];

    for (int i = t; i < 64*NNv; i += 256) {
        int atom = row0 + (i >> 6);
        int e = atom*NNv + (i & 63);
        int b = atom >> 10;
        int nb = nbr[e];
        const float* pi = pos + (size_t)atom*3;
        const float* pj = pos + (size_t)((b<<10) + nb)*3;
        const float* o  = off + (size_t)e*3;
        const float* c  = cell + b*9;
        float dx = pj[0]-pi[0] + o[0]*c[0] + o[1]*c[3] + o[2]*c[6];
        float dy = pj[1]-pi[1] + o[0]*c[1] + o[1]*c[4] + o[2]*c[7];
        float dz = pj[2]-pi[2] + o[0]*c[2] + o[1]*c[5] + o[2]*c[8];
        float d2 = dx*dx + dy*dy + dz*dz;
        g_r[e] = (d2 > 0.0f) ? sqrtf(d2) : 0.0f;
    }
    __syncthreads();

    #pragma unroll
    for (int r = 0; r < 32; ++r) {
        int row = r0 + r;
        float val = emb[(size_t)zs[row]*Fv + f];
        bufA[row*Fv + f] = val;
        x[(size_t)(row0 + row)*Fv + f] = val;
    }
    __syncthreads();

    float out[32];
    gemm_block<32>(bufA, W3, f, r0, out);
    #pragma unroll
    for (int r = 0; r < 32; ++r)
        g_y[(size_t)(row0 + r0 + r)*Fv + f] = __float2bfloat16(out[r]);
}

// ---------------- kernel 2: mma.sync fused filter-net + cfconv ----------------
// R10 structure (non-interleaved Mt, ping-pong VSM, 1 barrier/tile), with
// b1 fragments via gmem LDG (bias folded at k=25) and no bias smem.
// NO register cap — occupancy resolved at launch via occupancy query.
__global__ __launch_bounds__(128)
void edge_mma_kernel(int layer, const float* __restrict__ fw2,
                     const float* __restrict__ fb2,
                     const int* __restrict__ nbr, const float* __restrict__ msk)
{
    extern __shared__ __align__(16) char sm[];
    __nv_bfloat16* YT   = (__nv_bfloat16*)(sm + OFF_YT);     // [128][136]
    __nv_bfloat16* FW2T = (__nv_bfloat16*)(sm + OFF_FW2T);   // [128][144] quad-packed
    float* VSMB = (float*)(sm + OFF_VSM);                    // 2 x [4][128]

    const int t    = threadIdx.x;
    const int w    = t >> 5;
    const int lane = t & 31;
    const int qr   = lane >> 2;   // 0..7
    const int qc   = lane & 3;    // 0..3
    const uint32_t yt_base = s2u(YT);
    const uint2* __restrict__ b1p = g_b1pack[layer];

    // ---- per-layer setup: fw2^T quad-packed ----
    {
        const int f = t;
        #pragma unroll 2
        for (int s = 0; s < 8; ++s)
            for (int q2 = 0; q2 < 4; ++q2)
                #pragma unroll
                for (int j = 0; j < 4; ++j) {
                    int k = 16*s + 2*q2 + (j >> 1)*8 + (j & 1);
                    FW2T[f*144 + s*16 + q2*4 + j] = __float2bfloat16(fw2[k*Fv + f]);
                }
    }
    __syncthreads();

    int par = 0;
    for (int bt = blockIdx.x; bt < NBT; bt += gridDim.x) {
        const int e0 = bt * 128;

        // ---- A: issue y-row stage (bf16) via cp.async; row t is warp-local ----
        {
            int nb = __ldg(nbr + e0 + t);
            int batch = (e0 + t) >> 16;
            const __nv_bfloat16* src = g_y + ((size_t)batch << 17) + (size_t)nb * Fv;
            uint32_t dst = yt_base + (uint32_t)t * 272u;
            #pragma unroll
            for (int j = 0; j < 16; ++j)
                cp16(dst + 16u*j, (const char*)src + 16*j);
            asm volatile("cp.async.commit_group;" ::: "memory");
        }

        // ---- B: GEMM1 -> A2 fragments (both M-tiles) ----
        uint32_t A2[2][8][4];
        float mk[2][2];
        #pragma unroll
        for (int Mt = 0; Mt < 2; ++Mt) {
            const int rg = e0 + 32*w + 16*Mt + qr;
            const float rr0 = __ldg(g_r + rg);
            const float rr1 = __ldg(g_r + rg + 8);
            const float m0  = __ldg(msk + rg);
            const float m1  = __ldg(msk + rg + 8);
            mk[Mt][0] = m0; mk[Mt][1] = m1;
            const ull Mv0 = pack2(m0, m0), Mv1 = pack2(m1, m1);
            const ull ML0 = pack2(-LN2c*m0, -LN2c*m0), ML1 = pack2(-LN2c*m1, -LN2c*m1);

            // gaussians (+bias column at k=25) -> A fragments
            uint32_t Af[2][4];
            #pragma unroll
            for (int s = 0; s < 2; ++s) {
                const int g = 2*qc + 16*s;
                Af[s][0] = bf16pk(gval(rr0, g  ), gval(rr0, g+1));
                Af[s][1] = bf16pk(gval(rr1, g  ), gval(rr1, g+1));
                Af[s][2] = bf16pk(gval(rr0, g+8), gval(rr0, g+9));
                Af[s][3] = bf16pk(gval(rr1, g+8), gval(rr1, g+9));
            }

            #pragma unroll
            for (int s2 = 0; s2 < 8; ++s2) {
                #pragma unroll
                for (int nn = 0; nn < 2; ++nn) {
                    const int n = 2*s2 + nn;
                    float acc[4] = {0.0f, 0.0f, 0.0f, 0.0f};
                    uint2 u0 = __ldg(b1p + n*32 + lane);
                    uint2 u1 = __ldg(b1p + 512 + n*32 + lane);
                    mma_bf16(acc, Af[0], (const uint32_t*)&u0);
                    mma_bf16(acc, Af[1], (const uint32_t*)&u1);
                    A2[Mt][s2][2*nn    ] = ssp2(acc[0], acc[1], Mv0, ML0);
                    A2[Mt][s2][2*nn + 1] = ssp2(acc[2], acc[3], Mv1, ML1);
                }
            }
        }

        // ---- C: YT ready (warp-local rows only) ----
        asm volatile("cp.async.wait_group 0;" ::: "memory");
        __syncwarp();

        float* VSM = VSMB + par * 512;

        // ---- D/E: GEMM2 (K=128) + epilogue with analytic fb2 ----
        #pragma unroll
        for (int ch = 0; ch < 4; ++ch) {
            float acc2[2][4][4];
            #pragma unroll
            for (int Mt = 0; Mt < 2; ++Mt)
                #pragma unroll
                for (int n = 0; n < 4; ++n)
                    #pragma unroll
                    for (int i = 0; i < 4; ++i) acc2[Mt][n][i] = 0.0f;

            #pragma unroll
            for (int s = 0; s < 8; ++s) {
                #pragma unroll
                for (int n = 0; n < 4; ++n) {
                    int fB = 32*ch + 8*n + qr;
                    uint2 bb = *(const uint2*)(FW2T + fB*144 + s*16 + qc*4);
                    mma_bf16(acc2[0][n], A2[0][s], (const uint32_t*)&bb);
                    mma_bf16(acc2[1][n], A2[1][s], (const uint32_t*)&bb);
                }
            }

            float vp[8];
            #pragma unroll
            for (int i = 0; i < 8; ++i) vp[i] = 0.0f;
            #pragma unroll
            for (int Mt = 0; Mt < 2; ++Mt) {
                const int rl = 32*w + 16*Mt + qr;
                const float m0 = mk[Mt][0], m1 = mk[Mt][1];
                #pragma unroll
                for (int n = 0; n < 4; ++n) {
                    int fc = 32*ch + 8*n + 2*qc;
                    uint32_t y0 = *(const uint32_t*)(YT + rl*136 + fc);
                    uint32_t y1 = *(const uint32_t*)(YT + (rl+8)*136 + fc);
                    float2 f0 = bf2f(y0);
                    float2 f1 = bf2f(y1);
                    float2 fb = __ldg((const float2*)(fb2 + fc));
                    float t0 = fmaf(m1, f1.x, m0*f0.x);
                    float t1 = fmaf(m1, f1.y, m0*f0.y);
                    vp[2*n]   = fmaf(acc2[Mt][n][0], f0.x,
                                fmaf(acc2[Mt][n][2], f1.x,
                                fmaf(fb.x, t0, vp[2*n])));
                    vp[2*n+1] = fmaf(acc2[Mt][n][1], f0.y,
                                fmaf(acc2[Mt][n][3], f1.y,
                                fmaf(fb.y, t1, vp[2*n+1])));
                }
            }
            #pragma unroll
            for (int i = 0; i < 8; ++i) {
                vp[i] += __shfl_xor_sync(0xffffffffu, vp[i], 4);
                vp[i] += __shfl_xor_sync(0xffffffffu, vp[i], 8);
                vp[i] += __shfl_xor_sync(0xffffffffu, vp[i], 16);
            }
            if (lane < 4) {
                #pragma unroll
                for (int n = 0; n < 4; ++n) {
                    VSM[w*128 + 32*ch + 8*n + 2*lane    ] = vp[2*n];
                    VSM[w*128 + 32*ch + 8*n + 2*lane + 1] = vp[2*n+1];
                }
            }
        }

        // ---- F: single barrier; G: cross-warp combine -> g_v ----
        __syncthreads();
        #pragma unroll
        for (int a = 0; a < 2; ++a)
            g_v[(size_t)(2*bt + a)*Fv + t] =
                VSM[(2*a)*128 + t] + VSM[(2*a+1)*128 + t];
        par ^= 1;
    }
}

// ---------------- kernel 3: x += dense(ssp(f2out(v)))  [+ next-layer in2f] ----------------
template<int DO_Y>
__global__ __launch_bounds__(256)
void fused_post(const float* __restrict__ W1, const float* __restrict__ B1,
                const float* __restrict__ W2, const float* __restrict__ B2,
                const float* __restrict__ W3, float* __restrict__ x)
{
    extern __shared__ float fsm[];
    float* bufA = fsm;              // [32][128]
    float* bufB = fsm + 32*Fv;      // [32][128]
    const int t = threadIdx.x;
    const int f = t & 127, q = t >> 7;
    const int row0 = blockIdx.x * 32;
    const int r0 = q * 16;

    {   // load v tile
        const float4* src = (const float4*)(g_v + (size_t)row0 * Fv);
        float4* dst = (float4*)bufA;
        #pragma unroll
        for (int i = 0; i < 4; ++i) dst[t + 256*i] = src[t + 256*i];
    }
    __syncthreads();

    float out[16];
    gemm_block<16>(bufA, W1, f, r0, out);
    {
        float b = __ldg(B1 + f);
        #pragma unroll
        for (int r = 0; r < 16; ++r)
            bufB[(r0 + r)*Fv + f] = ssp(out[r] + b);
    }
    __syncthreads();

    gemm_block<16>(bufB, W2, f, r0, out);
    {
        float b = __ldg(B2 + f);
        #pragma unroll
        for (int r = 0; r < 16; ++r) {
            size_t gi = (size_t)(row0 + r0 + r)*Fv + f;
            float xn = x[gi] + out[r] + b;
            x[gi] = xn;
            if (DO_Y) bufA[(r0 + r)*Fv + f] = xn;
        }
    }
    if (DO_Y) {
        __syncthreads();
        gemm_block<16>(bufA, W3, f, r0, out);
        #pragma unroll
        for (int r = 0; r < 16; ++r)
            g_y[(size_t)(row0 + r0 + r)*Fv + f] = __float2bfloat16(out[r]);
    }
}

// ---------------- launcher ----------------
extern "C" void kernel_launch(void* const* d_in, const int* in_sizes, int n_in,
                              void* d_out, int out_size)
{
    const int*   zA   = (const int*)  d_in[0];
    const float* pos  = (const float*)d_in[1];
    const float* cell = (const float*)d_in[2];
    const float* off  = (const float*)d_in[3];
    const int*   nbr  = (const int*)  d_in[4];
    const float* msk  = (const float*)d_in[5];
    const float* emb  = (const float*)d_in[6];
    const float* fw1  = (const float*)d_in[7];
    const float* fb1  = (const float*)d_in[8];
    const float* fw2  = (const float*)d_in[9];
    const float* fb2  = (const float*)d_in[10];
    const float* i2f  = (const float*)d_in[11];
    const float* f2o  = (const float*)d_in[12];
    const float* f2ob = (const float*)d_in[13];
    const float* dw   = (const float*)d_in[14];
    const float* db   = (const float*)d_in[15];
    float* x = (float*)d_out;

    cudaFuncSetAttribute(edge_mma_kernel,
                         cudaFuncAttributeMaxDynamicSharedMemorySize, SMEM_EDGE);
    cudaFuncSetAttribute(fused_post<1>,
                         cudaFuncAttributeMaxDynamicSharedMemorySize, 32768);
    cudaFuncSetAttribute(fused_post<0>,
                         cudaFuncAttributeMaxDynamicSharedMemorySize, 32768);

    // size the persistent edge grid to actual occupancy (no register cap)
    int nb = 2;
    cudaOccupancyMaxActiveBlocksPerMultiprocessor(&nb, edge_mma_kernel, 128, SMEM_EDGE);
    if (nb < 1) nb = 1;
    int edge_grid = nb * NSM;
    if (edge_grid > NBT) edge_grid = NBT;

    pack_fw1_kernel<<<Lv, 1024>>>(fw1, fb1);
    init_y_kernel<<<(Bv*Av)/64, 256>>>(zA, pos, cell, off, nbr, emb, i2f, x);
    for (int l = 0; l < Lv; ++l) {
        edge_mma_kernel<<<edge_grid, 128, SMEM_EDGE>>>(
            l, fw2 + (size_t)l*Fv*Fv, fb2 + (size_t)l*Fv, nbr, msk);
        if (l < Lv - 1)
            fused_post<1><<<(Bv*Av)/32, 256, 32768>>>(
                f2o + (size_t)l*Fv*Fv, f2ob + (size_t)l*Fv,
                dw  + (size_t)l*Fv*Fv, db   + (size_t)l*Fv,
                i2f + (size_t)(l+1)*Fv*Fv, x);
        else
            fused_post<0><<<(Bv*Av)/32, 256, 32768>>>(
                f2o + (size_t)l*Fv*Fv, f2ob + (size_t)l*Fv,
                dw  + (size_t)l*Fv*Fv, db   + (size_t)l*Fv,
                (const float*)nullptr, x);
    }
}

// round 14
// speedup vs baseline: 1.0877x; 1.0218x over previous
#include <cuda_runtime.h>
#include <cuda_bf16.h>
#include <cstdint>

#define Bv 8
#define Av 1024
#define NNv 64
#define Gv 25
#define Fv 128
#define Lv 3
#define NBT 4096            // tiles: 2 atoms / 128 edges each
#define EDGE_GRID 304

#define WIDTHc (5.0f/24.0f)
#define COEFFc (-0.5f/(WIDTHc*WIDTHc))
#define LN2c 0.6931471805599453f

// ---- dynamic smem offsets (bytes) for edge kernel (128-thr CTA, 2 CTA/SM) ----
#define OFF_YT   0          // bf16 [128 e][136]  stride 272B  (34816 B)
#define OFF_FW2T 34816      // bf16 [128 f][144]  quad-packed  (36864 B)
#define OFF_FB1  71680      // f32 [128] (512 B)
#define OFF_FB2  72192      // f32 [128] (512 B)
#define OFF_VSM  72704      // f32 2 x [4][128] ping-pong (4096 B)
#define SMEM_EDGE 76800

typedef unsigned long long ull;

// ---------------- scratch ----------------
__device__ __nv_bfloat16 g_y[Bv*Av*Fv];
__device__ float g_v[Bv*Av*Fv];
__device__ float g_r[Bv*Av*NNv];
__device__ int g_tctr[Lv];             // dynamic tile counters (zeroed in init_y)

// ---------------- helpers ----------------
__device__ __forceinline__ float ssp(float x) {
    float u = __expf(-fabsf(x));
    float p = u*(0.99949556f + u*(-0.49190896f + u*(0.28947478f
              + u*(-0.13606275f + u*0.03215845f))));
    return fmaxf(x, 0.0f) + p - LN2c;
}
__device__ __forceinline__ uint32_t s2u(const void* p) {
    uint32_t a;
    asm("{ .reg .u64 t; cvta.to.shared.u64 t, %1; cvt.u32.u64 %0, t; }" : "=r"(a) : "l"(p));
    return a;
}
__device__ __forceinline__ uint32_t bf16pk(float lo, float hi) {
    uint32_t r;
    asm("cvt.rn.bf16x2.f32 %0, %1, %2;" : "=r"(r) : "f"(hi), "f"(lo));
    return r;
}
__device__ __forceinline__ float2 bf2f(uint32_t p) {
    float2 r;
    r.x = __uint_as_float(p << 16);
    r.y = __uint_as_float(p & 0xffff0000u);
    return r;
}
__device__ __forceinline__ void mma_bf16(float* d, const uint32_t* a, const uint32_t* b) {
    asm volatile(
        "mma.sync.aligned.m16n8k16.row.col.f32.bf16.bf16.f32 "
        "{%0,%1,%2,%3}, {%4,%5,%6,%7}, {%8,%9}, {%0,%1,%2,%3};"
        : "+f"(d[0]), "+f"(d[1]), "+f"(d[2]), "+f"(d[3])
        : "r"(a[0]), "r"(a[1]), "r"(a[2]), "r"(a[3]), "r"(b[0]), "r"(b[1]));
}
__device__ __forceinline__ void cp16(uint32_t dst, const void* src) {
    asm volatile("cp.async.ca.shared.global [%0], [%1], 16;" :: "r"(dst), "l"(src) : "memory");
}
__device__ __forceinline__ ull fma2(ull a, ull b, ull c) {
    ull d;
    asm("fma.rn.f32x2 %0, %1, %2, %3;" : "=l"(d) : "l"(a), "l"(b), "l"(c));
    return d;
}
__device__ __forceinline__ ull pack2(float lo, float hi) {
    ull d;
    asm("mov.b64 %0, {%1, %2};" : "=l"(d) : "f"(lo), "f"(hi));
    return d;
}
__device__ __forceinline__ float hsum2(ull v) {
    float lo, hi;
    asm("mov.b64 {%0, %1}, %2;" : "=f"(lo), "=f"(hi) : "l"(v));
    return lo + hi;
}
// packed ssp pair -> bf16x2: ((softplus(x0)-ln2)*m, (softplus(x1)-ln2)*m)
__device__ __forceinline__ uint32_t ssp2(float x0, float x1, ull Mv, ull MLv) {
    float u0 = __expf(-fabsf(x0));
    float u1 = __expf(-fabsf(x1));
    ull U = pack2(u0, u1);
    ull tt = fma2(U, pack2(0.03215845f, 0.03215845f), pack2(-0.13606275f, -0.13606275f));
    tt = fma2(U, tt, pack2(0.28947478f, 0.28947478f));
    tt = fma2(U, tt, pack2(-0.49190896f, -0.49190896f));
    tt = fma2(U, tt, pack2(0.99949556f, 0.99949556f));
    ull B = pack2(fmaxf(x0, 0.0f), fmaxf(x1, 0.0f));
    ull R = fma2(U, tt, B);
    R = fma2(R, Mv, MLv);
    float lo, hi;
    asm("mov.b64 {%0, %1}, %2;" : "=f"(lo), "=f"(hi) : "l"(R));
    return bf16pk(lo, hi);
}

// R-rows x 128x128 GEMM core: thread owns column f, rows [r0, r0+R).
// k-blocked weight prefetch: 16 LDGs in flight (MLP 16) per 8-kp block.
template<int R>
__device__ __forceinline__ void gemm_block(const float* sbuf, const float* __restrict__ W,
                                           int f, int r0, float* out)
{
    ull acc[R];
    #pragma unroll
    for (int i = 0; i < R; ++i) acc[i] = 0ull;
    const ull* xs = (const ull*)sbuf;
    #pragma unroll
    for (int kb = 0; kb < 64; kb += 8) {
        ull wp[8];
        #pragma unroll
        for (int j = 0; j < 8; ++j)
            wp[j] = pack2(__ldg(W + 2*(kb+j)*Fv + f), __ldg(W + (2*(kb+j)+1)*Fv + f));
        #pragma unroll
        for (int j = 0; j < 8; ++j)
            #pragma unroll
            for (int r = 0; r < R; ++r)
                acc[r] = fma2(xs[(r0 + r)*64 + kb + j], wp[j], acc[r]);
    }
    #pragma unroll
    for (int r = 0; r < R; ++r) out[r] = hsum2(acc[r]);
}

// ---------------- kernel 0: embedding + distances + y0 GEMM ----------------
__global__ __launch_bounds__(256)
void init_y_kernel(const int* __restrict__ zA, const float* __restrict__ pos,
                   const float* __restrict__ cell, const float* __restrict__ off,
                   const int* __restrict__ nbr, const float* __restrict__ emb,
                   const float* __restrict__ W3, float* __restrict__ x)
{
    __shared__ float bufA[64*Fv];
    __shared__ int zs[64];
    const int t = threadIdx.x;
    const int f = t & 127, q = t >> 7;
    const int row0 = blockIdx.x * 64;
    const int r0 = q * 32;

    if (blockIdx.x == 0 && t < Lv) g_tctr[t] = 0;   // reset edge tile counters
    if (t < 64) zs[t] = zA[row0 + t];

    for (int i = t; i < 64*NNv; i += 256) {
        int atom = row0 + (i >> 6);
        int e = atom*NNv + (i & 63);
        int b = atom >> 10;
        int nb = nbr[e];
        const float* pi = pos + (size_t)atom*3;
        const float* pj = pos + (size_t)((b<<10) + nb)*3;
        const float* o  = off + (size_t)e*3;
        const float* c  = cell + b*9;
        float dx = pj[0]-pi[0] + o[0]*c[0] + o[1]*c[3] + o[2]*c[6];
        float dy = pj[1]-pi[1] + o[0]*c[1] + o[1]*c[4] + o[2]*c[7];
        float dz = pj[2]-pi[2] + o[0]*c[2] + o[1]*c[5] + o[2]*c[8];
        float d2 = dx*dx + dy*dy + dz*dz;
        g_r[e] = (d2 > 0.0f) ? sqrtf(d2) : 0.0f;
    }
    __syncthreads();

    #pragma unroll
    for (int r = 0; r < 32; ++r) {
        int row = r0 + r;
        float val = emb[(size_t)zs[row]*Fv + f];
        bufA[row*Fv + f] = val;
        x[(size_t)(row0 + row)*Fv + f] = val;
    }
    __syncthreads();

    float out[32];
    gemm_block<32>(bufA, W3, f, r0, out);
    #pragma unroll
    for (int r = 0; r < 32; ++r)
        g_y[(size_t)(row0 + r0 + r)*Fv + f] = __float2bfloat16(out[r]);
}

// ---------------- kernel 2: mma.sync fused filter-net + cfconv ----------------
// R10 structure exactly (2 atoms/CTA, b1f registers, quad-packed FW2T, K=128,
// analytic fb2, ping-pong VSM, 1 barrier/tile) + dynamic tile scheduler with
// early prefetch of the next tile index.
__global__ __launch_bounds__(128)
void edge_mma_kernel(int layer,
                     const float* __restrict__ fw1, const float* __restrict__ fb1,
                     const float* __restrict__ fw2, const float* __restrict__ fb2,
                     const int* __restrict__ nbr, const float* __restrict__ msk)
{
    extern __shared__ __align__(16) char sm[];
    __nv_bfloat16* YT   = (__nv_bfloat16*)(sm + OFF_YT);     // [128][136]
    __nv_bfloat16* FW2T = (__nv_bfloat16*)(sm + OFF_FW2T);   // [128][144] quad-packed
    float* FB1  = (float*)(sm + OFF_FB1);
    float* FB2  = (float*)(sm + OFF_FB2);
    float* VSMB = (float*)(sm + OFF_VSM);                    // 2 x [4][128]
    __shared__ int s_bt[2];

    const int t    = threadIdx.x;
    const int w    = t >> 5;
    const int lane = t & 31;
    const int qr   = lane >> 2;   // 0..7
    const int qc   = lane & 3;    // 0..3
    const uint32_t yt_base = s2u(YT);

    // ---- per-layer setup ----
    FB1[t] = fb1[t];
    FB2[t] = fb2[t];
    {   // fw2^T quad-packed: FW2T[f*144 + s*16 + q2*4 + j] = fw2[k][f],
        // k = 16s + 2q2 + (j>>1)*8 + (j&1)
        const int f = t;
        #pragma unroll 2
        for (int s = 0; s < 8; ++s)
            for (int q2 = 0; q2 < 4; ++q2)
                #pragma unroll
                for (int j = 0; j < 4; ++j) {
                    int k = 16*s + 2*q2 + (j >> 1)*8 + (j & 1);
                    FW2T[f*144 + s*16 + q2*4 + j] = __float2bfloat16(fw2[k*Fv + f]);
                }
    }
    // fw1 B-fragments in registers: [kstep s][ntile n][2]
    uint32_t b1f[2][16][2];
    #pragma unroll
    for (int s = 0; s < 2; ++s) {
        #pragma unroll
        for (int n = 0; n < 16; ++n) {
            int g = 2*qc + 16*s;
            int fn = 8*n + qr;
            float w00 = (g   < Gv) ? fw1[(g  )*Fv + fn] : 0.0f;
            float w01 = (g+1 < Gv) ? fw1[(g+1)*Fv + fn] : 0.0f;
            float w10 = (g+8 < Gv) ? fw1[(g+8)*Fv + fn] : 0.0f;
            float w11 = (g+9 < Gv) ? fw1[(g+9)*Fv + fn] : 0.0f;
            b1f[s][n][0] = bf16pk(w00, w01);
            b1f[s][n][1] = bf16pk(w10, w11);
        }
    }
    if (t == 0) s_bt[0] = atomicAdd(&g_tctr[layer], 1);
    __syncthreads();

    int par = 0, sp = 0;
    for (;;) {
        const int bt = s_bt[sp];
        if (bt >= NBT) break;
        const int e0 = bt * 128;

        // ---- A: issue y-row stage (bf16) via cp.async; row t is warp-local ----
        {
            int nb = __ldg(nbr + e0 + t);
            int batch = (e0 + t) >> 16;
            const __nv_bfloat16* src = g_y + ((size_t)batch << 17) + (size_t)nb * Fv;
            uint32_t dst = yt_base + (uint32_t)t * 272u;
            #pragma unroll
            for (int j = 0; j < 16; ++j)
                cp16(dst + 16u*j, (const char*)src + 16*j);
            asm volatile("cp.async.commit_group;" ::: "memory");
        }
        // prefetch next tile index (ATOMG latency hidden behind GEMM1)
        if (t == 0) s_bt[sp ^ 1] = atomicAdd(&g_tctr[layer], 1);

        // ---- B: GEMM1 -> A2 fragments; r/mask direct from gmem ----
        uint32_t A2[2][8][4];
        float mk[2][2];
        #pragma unroll
        for (int Mt = 0; Mt < 2; ++Mt) {
            const int rg = e0 + 32*w + 16*Mt + qr;
            const float rr0 = __ldg(g_r + rg);
            const float rr1 = __ldg(g_r + rg + 8);
            const float m0  = __ldg(msk + rg);
            const float m1  = __ldg(msk + rg + 8);
            mk[Mt][0] = m0; mk[Mt][1] = m1;
            const ull Mv0 = pack2(m0, m0), Mv1 = pack2(m1, m1);
            const ull ML0 = pack2(-LN2c*m0, -LN2c*m0), ML1 = pack2(-LN2c*m1, -LN2c*m1);

            uint32_t Af[2][4];
            #pragma unroll
            for (int s = 0; s < 2; ++s) {
                const int g = 2*qc + 16*s;
                float d, e00, e01, e02, e03, e10, e11, e12, e13;
                d = rr0 - (g  )*WIDTHc; e00 = (g   < Gv) ? __expf(COEFFc*d*d) : 0.0f;
                d = rr0 - (g+1)*WIDTHc; e01 = (g+1 < Gv) ? __expf(COEFFc*d*d) : 0.0f;
                d = rr0 - (g+8)*WIDTHc; e02 = (g+8 < Gv) ? __expf(COEFFc*d*d) : 0.0f;
                d = rr0 - (g+9)*WIDTHc; e03 = (g+9 < Gv) ? __expf(COEFFc*d*d) : 0.0f;
                d = rr1 - (g  )*WIDTHc; e10 = (g   < Gv) ? __expf(COEFFc*d*d) : 0.0f;
                d = rr1 - (g+1)*WIDTHc; e11 = (g+1 < Gv) ? __expf(COEFFc*d*d) : 0.0f;
                d = rr1 - (g+8)*WIDTHc; e12 = (g+8 < Gv) ? __expf(COEFFc*d*d) : 0.0f;
                d = rr1 - (g+9)*WIDTHc; e13 = (g+9 < Gv) ? __expf(COEFFc*d*d) : 0.0f;
                Af[s][0] = bf16pk(e00, e01);
                Af[s][1] = bf16pk(e10, e11);
                Af[s][2] = bf16pk(e02, e03);
                Af[s][3] = bf16pk(e12, e13);
            }

            #pragma unroll
            for (int s2 = 0; s2 < 8; ++s2) {
                #pragma unroll
                for (int nn = 0; nn < 2; ++nn) {
                    const int n = 2*s2 + nn;
                    float acc[4] = {0.0f, 0.0f, 0.0f, 0.0f};
                    mma_bf16(acc, Af[0], b1f[0][n]);
                    mma_bf16(acc, Af[1], b1f[1][n]);
                    float2 b12 = *(const float2*)(FB1 + 8*n + 2*qc);
                    A2[Mt][s2][2*nn    ] = ssp2(acc[0] + b12.x, acc[1] + b12.y, Mv0, ML0);
                    A2[Mt][s2][2*nn + 1] = ssp2(acc[2] + b12.x, acc[3] + b12.y, Mv1, ML1);
                }
            }
        }

        // ---- C: YT ready (warp-local rows only) ----
        asm volatile("cp.async.wait_group 0;" ::: "memory");
        __syncwarp();

        float* VSM = VSMB + par * 512;

        // ---- D/E: GEMM2 (K=128) + epilogue with analytic fb2 ----
        #pragma unroll
        for (int ch = 0; ch < 4; ++ch) {
            float acc2[2][4][4];
            #pragma unroll
            for (int Mt = 0; Mt < 2; ++Mt)
                #pragma unroll
                for (int n = 0; n < 4; ++n)
                    #pragma unroll
                    for (int i = 0; i < 4; ++i) acc2[Mt][n][i] = 0.0f;

            #pragma unroll
            for (int s = 0; s < 8; ++s) {
                #pragma unroll
                for (int n = 0; n < 4; ++n) {
                    int fB = 32*ch + 8*n + qr;
                    uint2 bb = *(const uint2*)(FW2T + fB*144 + s*16 + qc*4);
                    mma_bf16(acc2[0][n], A2[0][s], (const uint32_t*)&bb);
                    mma_bf16(acc2[1][n], A2[1][s], (const uint32_t*)&bb);
                }
            }

            float vp[8];
            #pragma unroll
            for (int i = 0; i < 8; ++i) vp[i] = 0.0f;
            #pragma unroll
            for (int Mt = 0; Mt < 2; ++Mt) {
                const int rl = 32*w + 16*Mt + qr;
                const float m0 = mk[Mt][0], m1 = mk[Mt][1];
                #pragma unroll
                for (int n = 0; n < 4; ++n) {
                    int fc = 32*ch + 8*n + 2*qc;
                    uint32_t y0 = *(const uint32_t*)(YT + rl*136 + fc);
                    uint32_t y1 = *(const uint32_t*)(YT + (rl+8)*136 + fc);
                    float2 f0 = bf2f(y0);
                    float2 f1 = bf2f(y1);
                    float2 fb = *(const float2*)(FB2 + fc);
                    float t0 = fmaf(m1, f1.x, m0*f0.x);
                    float t1 = fmaf(m1, f1.y, m0*f0.y);
                    vp[2*n]   = fmaf(acc2[Mt][n][0], f0.x,
                                fmaf(acc2[Mt][n][2], f1.x,
                                fmaf(fb.x, t0, vp[2*n])));
                    vp[2*n+1] = fmaf(acc2[Mt][n][1], f0.y,
                                fmaf(acc2[Mt][n][3], f1.y,
                                fmaf(fb.y, t1, vp[2*n+1])));
                }
            }
            #pragma unroll
            for (int i = 0; i < 8; ++i) {
                vp[i] += __shfl_xor_sync(0xffffffffu, vp[i], 4);
                vp[i] += __shfl_xor_sync(0xffffffffu, vp[i], 8);
                vp[i] += __shfl_xor_sync(0xffffffffu, vp[i], 16);
            }
            if (lane < 4) {
                #pragma unroll
                for (int n = 0; n < 4; ++n) {
                    VSM[w*128 + 32*ch + 8*n + 2*lane    ] = vp[2*n];
                    VSM[w*128 + 32*ch + 8*n + 2*lane + 1] = vp[2*n+1];
                }
            }
        }

        // ---- F: single barrier; G: cross-warp combine -> g_v ----
        __syncthreads();
        #pragma unroll
        for (int a = 0; a < 2; ++a)
            g_v[(size_t)(2*bt + a)*Fv + t] =
                VSM[(2*a)*128 + t] + VSM[(2*a+1)*128 + t];
        par ^= 1;
        sp ^= 1;
    }
}

// ---------------- kernel 3: x += dense(ssp(f2out(v)))  [+ next-layer in2f] ----------------
template<int DO_Y>
__global__ __launch_bounds__(256)
void fused_post(const float* __restrict__ W1, const float* __restrict__ B1,
                const float* __restrict__ W2, const float* __restrict__ B2,
                const float* __restrict__ W3, float* __restrict__ x)
{
    extern __shared__ float fsm[];
    float* bufA = fsm;              // [32][128]
    float* bufB = fsm + 32*Fv;      // [32][128]
    const int t = threadIdx.x;
    const int f = t & 127, q = t >> 7;
    const int row0 = blockIdx.x * 32;
    const int r0 = q * 16;

    {   // load v tile
        const float4* src = (const float4*)(g_v + (size_t)row0 * Fv);
        float4* dst = (float4*)bufA;
        #pragma unroll
        for (int i = 0; i < 4; ++i) dst[t + 256*i] = src[t + 256*i];
    }
    __syncthreads();

    float out[16];
    gemm_block<16>(bufA, W1, f, r0, out);
    {
        float b = __ldg(B1 + f);
        #pragma unroll
        for (int r = 0; r < 16; ++r)
            bufB[(r0 + r)*Fv + f] = ssp(out[r] + b);
    }
    __syncthreads();

    gemm_block<16>(bufB, W2, f, r0, out);
    {
        float b = __ldg(B2 + f);
        #pragma unroll
        for (int r = 0; r < 16; ++r) {
            size_t gi = (size_t)(row0 + r0 + r)*Fv + f;
            float xn = x[gi] + out[r] + b;
            x[gi] = xn;
            if (DO_Y) bufA[(r0 + r)*Fv + f] = xn;
        }
    }
    if (DO_Y) {
        __syncthreads();
        gemm_block<16>(bufA, W3, f, r0, out);
        #pragma unroll
        for (int r = 0; r < 16; ++r)
            g_y[(size_t)(row0 + r0 + r)*Fv + f] = __float2bfloat16(out[r]);
    }
}

// ---------------- launcher ----------------
extern "C" void kernel_launch(void* const* d_in, const int* in_sizes, int n_in,
                              void* d_out, int out_size)
{
    const int*   zA   = (const int*)  d_in[0];
    const float* pos  = (const float*)d_in[1];
    const float* cell = (const float*)d_in[2];
    const float* off  = (const float*)d_in[3];
    const int*   nbr  = (const int*)  d_in[4];
    const float* msk  = (const float*)d_in[5];
    const float* emb  = (const float*)d_in[6];
    const float* fw1  = (const float*)d_in[7];
    const float* fb1  = (const float*)d_in[8];
    const float* fw2  = (const float*)d_in[9];
    const float* fb2  = (const float*)d_in[10];
    const float* i2f  = (const float*)d_in[11];
    const float* f2o  = (const float*)d_in[12];
    const float* f2ob = (const float*)d_in[13];
    const float* dw   = (const float*)d_in[14];
    const float* db   = (const float*)d_in[15];
    float* x = (float*)d_out;

    cudaFuncSetAttribute(edge_mma_kernel,
                         cudaFuncAttributeMaxDynamicSharedMemorySize, SMEM_EDGE);
    cudaFuncSetAttribute(fused_post<1>,
                         cudaFuncAttributeMaxDynamicSharedMemorySize, 32768);
    cudaFuncSetAttribute(fused_post<0>,
                         cudaFuncAttributeMaxDynamicSharedMemorySize, 32768);

    init_y_kernel<<<(Bv*Av)/64, 256>>>(zA, pos, cell, off, nbr, emb, i2f, x);
    for (int l = 0; l < Lv; ++l) {
        edge_mma_kernel<<<EDGE_GRID, 128, SMEM_EDGE>>>(
            l, fw1 + (size_t)l*Gv*Fv, fb1 + (size_t)l*Fv,
            fw2 + (size_t)l*Fv*Fv, fb2 + (size_t)l*Fv, nbr, msk);
        if (l < Lv - 1)
            fused_post<1><<<(Bv*Av)/32, 256, 32768>>>(
                f2o + (size_t)l*Fv*Fv, f2ob + (size_t)l*Fv,
                dw  + (size_t)l*Fv*Fv, db   + (size_t)l*Fv,
                i2f + (size_t)(l+1)*Fv*Fv, x);
        else
            fused_post<0><<<(Bv*Av)/32, 256, 32768>>>(
                f2o + (size_t)l*Fv*Fv, f2ob + (size_t)l*Fv,
                dw  + (size_t)l*Fv*Fv, db   + (size_t)l*Fv,
                (const float*)nullptr, x);
    }
}

// round 15
// speedup vs baseline: 1.1260x; 1.0352x over previous
#include <cuda_runtime.h>
#include <cuda_bf16.h>
#include <cstdint>

#define Bv 8
#define Av 1024
#define NNv 64
#define Gv 25
#define Fv 128
#define Lv 3
#define NBT 4096            // tiles: 2 atoms / 128 edges each
#define EDGE_GRID 304

#define WIDTHc (5.0f/24.0f)
#define COEFFc (-0.5f/(WIDTHc*WIDTHc))
#define LN2c 0.6931471805599453f

// ---- dynamic smem offsets (bytes) for edge kernel (128-thr CTA, 2 CTA/SM) ----
#define OFF_YT   0          // bf16 [128 e][136]  stride 272B  (34816 B)
#define OFF_FW2T 34816      // bf16 [128 f][144]  quad-packed  (36864 B)
#define OFF_FB1  71680      // f32 [128] (512 B)
#define OFF_FB2  72192      // f32 [128] (512 B)
#define OFF_VSM  72704      // f32 2 x [4][128] ping-pong (4096 B)
#define SMEM_EDGE 76800

typedef unsigned long long ull;

// ---------------- scratch ----------------
__device__ __nv_bfloat16 g_y[Bv*Av*Fv];
__device__ float g_v[Bv*Av*Fv];
__device__ float g_r[Bv*Av*NNv];

// ---------------- helpers ----------------
__device__ __forceinline__ float ssp(float x) {
    float u = __expf(-fabsf(x));
    float p = u*(0.99949556f + u*(-0.49190896f + u*(0.28947478f
              + u*(-0.13606275f + u*0.03215845f))));
    return fmaxf(x, 0.0f) + p - LN2c;
}
__device__ __forceinline__ uint32_t s2u(const void* p) {
    uint32_t a;
    asm("{ .reg .u64 t; cvta.to.shared.u64 t, %1; cvt.u32.u64 %0, t; }" : "=r"(a) : "l"(p));
    return a;
}
__device__ __forceinline__ uint32_t bf16pk(float lo, float hi) {
    uint32_t r;
    asm("cvt.rn.bf16x2.f32 %0, %1, %2;" : "=r"(r) : "f"(hi), "f"(lo));
    return r;
}
__device__ __forceinline__ float2 bf2f(uint32_t p) {
    float2 r;
    r.x = __uint_as_float(p << 16);
    r.y = __uint_as_float(p & 0xffff0000u);
    return r;
}
__device__ __forceinline__ void mma_bf16(float* d, const uint32_t* a, const uint32_t* b) {
    asm volatile(
        "mma.sync.aligned.m16n8k16.row.col.f32.bf16.bf16.f32 "
        "{%0,%1,%2,%3}, {%4,%5,%6,%7}, {%8,%9}, {%0,%1,%2,%3};"
        : "+f"(d[0]), "+f"(d[1]), "+f"(d[2]), "+f"(d[3])
        : "r"(a[0]), "r"(a[1]), "r"(a[2]), "r"(a[3]), "r"(b[0]), "r"(b[1]));
}
__device__ __forceinline__ void cp16(uint32_t dst, const void* src) {
    asm volatile("cp.async.ca.shared.global [%0], [%1], 16;" :: "r"(dst), "l"(src) : "memory");
}
__device__ __forceinline__ ull fma2(ull a, ull b, ull c) {
    ull d;
    asm("fma.rn.f32x2 %0, %1, %2, %3;" : "=l"(d) : "l"(a), "l"(b), "l"(c));
    return d;
}
__device__ __forceinline__ ull pack2(float lo, float hi) {
    ull d;
    asm("mov.b64 %0, {%1, %2};" : "=l"(d) : "f"(lo), "f"(hi));
    return d;
}
__device__ __forceinline__ float hsum2(ull v) {
    float lo, hi;
    asm("mov.b64 {%0, %1}, %2;" : "=f"(lo), "=f"(hi) : "l"(v));
    return lo + hi;
}
// packed ssp pair -> bf16x2: ((softplus(x0)-ln2)*m, (softplus(x1)-ln2)*m)
__device__ __forceinline__ uint32_t ssp2(float x0, float x1, ull Mv, ull MLv) {
    float u0 = __expf(-fabsf(x0));
    float u1 = __expf(-fabsf(x1));
    ull U = pack2(u0, u1);
    ull tt = fma2(U, pack2(0.03215845f, 0.03215845f), pack2(-0.13606275f, -0.13606275f));
    tt = fma2(U, tt, pack2(0.28947478f, 0.28947478f));
    tt = fma2(U, tt, pack2(-0.49190896f, -0.49190896f));
    tt = fma2(U, tt, pack2(0.99949556f, 0.99949556f));
    ull B = pack2(fmaxf(x0, 0.0f), fmaxf(x1, 0.0f));
    ull R = fma2(U, tt, B);
    R = fma2(R, Mv, MLv);
    float lo, hi;
    asm("mov.b64 {%0, %1}, %2;" : "=f"(lo), "=f"(hi) : "l"(R));
    return bf16pk(lo, hi);
}

// R-rows x 128x128 GEMM core: thread owns column f, rows [r0, r0+R).
// k-blocked weight prefetch: 16 LDGs in flight (MLP 16) per 8-kp block.
template<int R>
__device__ __forceinline__ void gemm_block(const float* sbuf, const float* __restrict__ W,
                                           int f, int r0, float* out)
{
    ull acc[R];
    #pragma unroll
    for (int i = 0; i < R; ++i) acc[i] = 0ull;
    const ull* xs = (const ull*)sbuf;
    #pragma unroll
    for (int kb = 0; kb < 64; kb += 8) {
        ull wp[8];
        #pragma unroll
        for (int j = 0; j < 8; ++j)
            wp[j] = pack2(__ldg(W + 2*(kb+j)*Fv + f), __ldg(W + (2*(kb+j)+1)*Fv + f));
        #pragma unroll
        for (int j = 0; j < 8; ++j)
            #pragma unroll
            for (int r = 0; r < R; ++r)
                acc[r] = fma2(xs[(r0 + r)*64 + kb + j], wp[j], acc[r]);
    }
    #pragma unroll
    for (int r = 0; r < R; ++r) out[r] = hsum2(acc[r]);
}

// ---------------- kernel 0: embedding + distances + y0 GEMM ----------------
__global__ __launch_bounds__(256)
void init_y_kernel(const int* __restrict__ zA, const float* __restrict__ pos,
                   const float* __restrict__ cell, const float* __restrict__ off,
                   const int* __restrict__ nbr, const float* __restrict__ emb,
                   const float* __restrict__ W3, float* __restrict__ x)
{
    __shared__ float bufA[64*Fv];
    __shared__ int zs[64];
    const int t = threadIdx.x;
    const int f = t & 127, q = t >> 7;
    const int row0 = blockIdx.x * 64;
    const int r0 = q * 32;

    if (t < 64) zs[t] = zA[row0 + t];

    for (int i = t; i < 64*NNv; i += 256) {
        int atom = row0 + (i >> 6);
        int e = atom*NNv + (i & 63);
        int b = atom >> 10;
        int nb = nbr[e];
        const float* pi = pos + (size_t)atom*3;
        const float* pj = pos + (size_t)((b<<10) + nb)*3;
        const float* o  = off + (size_t)e*3;
        const float* c  = cell + b*9;
        float dx = pj[0]-pi[0] + o[0]*c[0] + o[1]*c[3] + o[2]*c[6];
        float dy = pj[1]-pi[1] + o[0]*c[1] + o[1]*c[4] + o[2]*c[7];
        float dz = pj[2]-pi[2] + o[0]*c[2] + o[1]*c[5] + o[2]*c[8];
        float d2 = dx*dx + dy*dy + dz*dz;
        g_r[e] = (d2 > 0.0f) ? sqrtf(d2) : 0.0f;
    }
    __syncthreads();

    #pragma unroll
    for (int r = 0; r < 32; ++r) {
        int row = r0 + r;
        float val = emb[(size_t)zs[row]*Fv + f];
        bufA[row*Fv + f] = val;
        x[(size_t)(row0 + row)*Fv + f] = val;
    }
    __syncthreads();

    float out[32];
    gemm_block<32>(bufA, W3, f, r0, out);
    #pragma unroll
    for (int r = 0; r < 32; ++r)
        g_y[(size_t)(row0 + r0 + r)*Fv + f] = __float2bfloat16(out[r]);
}

// ---------------- kernel 2: mma.sync fused filter-net + cfconv ----------------
// R10 edge kernel verbatim: 2 atoms/CTA, static grid-stride loop, b1f in
// registers, quad-packed FW2T (1 LDS.64/mma), K=128 GEMM2 (fb2 analytic),
// packed ssp2, cp.async YT staging, 1 barrier/tile, ping-pong VSM.
__global__ __launch_bounds__(128)
void edge_mma_kernel(const float* __restrict__ fw1, const float* __restrict__ fb1,
                     const float* __restrict__ fw2, const float* __restrict__ fb2,
                     const int* __restrict__ nbr, const float* __restrict__ msk)
{
    extern __shared__ __align__(16) char sm[];
    __nv_bfloat16* YT   = (__nv_bfloat16*)(sm + OFF_YT);     // [128][136]
    __nv_bfloat16* FW2T = (__nv_bfloat16*)(sm + OFF_FW2T);   // [128][144] quad-packed
    float* FB1  = (float*)(sm + OFF_FB1);
    float* FB2  = (float*)(sm + OFF_FB2);
    float* VSMB = (float*)(sm + OFF_VSM);                    // 2 x [4][128]

    const int t    = threadIdx.x;
    const int w    = t >> 5;
    const int lane = t & 31;
    const int qr   = lane >> 2;   // 0..7
    const int qc   = lane & 3;    // 0..3
    const uint32_t yt_base = s2u(YT);

    // ---- per-layer setup ----
    FB1[t] = fb1[t];
    FB2[t] = fb2[t];
    {   // fw2^T quad-packed: FW2T[f*144 + s*16 + q2*4 + j] = fw2[k][f],
        // k = 16s + 2q2 + (j>>1)*8 + (j&1)
        const int f = t;
        #pragma unroll 2
        for (int s = 0; s < 8; ++s)
            for (int q2 = 0; q2 < 4; ++q2)
                #pragma unroll
                for (int j = 0; j < 4; ++j) {
                    int k = 16*s + 2*q2 + (j >> 1)*8 + (j & 1);
                    FW2T[f*144 + s*16 + q2*4 + j] = __float2bfloat16(fw2[k*Fv + f]);
                }
    }
    // fw1 B-fragments in registers: [kstep s][ntile n][2]
    uint32_t b1f[2][16][2];
    #pragma unroll
    for (int s = 0; s < 2; ++s) {
        #pragma unroll
        for (int n = 0; n < 16; ++n) {
            int g = 2*qc + 16*s;
            int fn = 8*n + qr;
            float w00 = (g   < Gv) ? fw1[(g  )*Fv + fn] : 0.0f;
            float w01 = (g+1 < Gv) ? fw1[(g+1)*Fv + fn] : 0.0f;
            float w10 = (g+8 < Gv) ? fw1[(g+8)*Fv + fn] : 0.0f;
            float w11 = (g+9 < Gv) ? fw1[(g+9)*Fv + fn] : 0.0f;
            b1f[s][n][0] = bf16pk(w00, w01);
            b1f[s][n][1] = bf16pk(w10, w11);
        }
    }
    __syncthreads();

    int par = 0;
    for (int bt = blockIdx.x; bt < NBT; bt += gridDim.x) {
        const int e0 = bt * 128;

        // ---- A: issue y-row stage (bf16) via cp.async; row t is warp-local ----
        {
            int nb = __ldg(nbr + e0 + t);
            int batch = (e0 + t) >> 16;
            const __nv_bfloat16* src = g_y + ((size_t)batch << 17) + (size_t)nb * Fv;
            uint32_t dst = yt_base + (uint32_t)t * 272u;
            #pragma unroll
            for (int j = 0; j < 16; ++j)
                cp16(dst + 16u*j, (const char*)src + 16*j);
            asm volatile("cp.async.commit_group;" ::: "memory");
        }

        // ---- B: GEMM1 -> A2 fragments; r/mask direct from gmem ----
        uint32_t A2[2][8][4];
        float mk[2][2];
        #pragma unroll
        for (int Mt = 0; Mt < 2; ++Mt) {
            const int rg = e0 + 32*w + 16*Mt + qr;
            const float rr0 = __ldg(g_r + rg);
            const float rr1 = __ldg(g_r + rg + 8);
            const float m0  = __ldg(msk + rg);
            const float m1  = __ldg(msk + rg + 8);
            mk[Mt][0] = m0; mk[Mt][1] = m1;
            const ull Mv0 = pack2(m0, m0), Mv1 = pack2(m1, m1);
            const ull ML0 = pack2(-LN2c*m0, -LN2c*m0), ML1 = pack2(-LN2c*m1, -LN2c*m1);

            uint32_t Af[2][4];
            #pragma unroll
            for (int s = 0; s < 2; ++s) {
                const int g = 2*qc + 16*s;
                float d, e00, e01, e02, e03, e10, e11, e12, e13;
                d = rr0 - (g  )*WIDTHc; e00 = (g   < Gv) ? __expf(COEFFc*d*d) : 0.0f;
                d = rr0 - (g+1)*WIDTHc; e01 = (g+1 < Gv) ? __expf(COEFFc*d*d) : 0.0f;
                d = rr0 - (g+8)*WIDTHc; e02 = (g+8 < Gv) ? __expf(COEFFc*d*d) : 0.0f;
                d = rr0 - (g+9)*WIDTHc; e03 = (g+9 < Gv) ? __expf(COEFFc*d*d) : 0.0f;
                d = rr1 - (g  )*WIDTHc; e10 = (g   < Gv) ? __expf(COEFFc*d*d) : 0.0f;
                d = rr1 - (g+1)*WIDTHc; e11 = (g+1 < Gv) ? __expf(COEFFc*d*d) : 0.0f;
                d = rr1 - (g+8)*WIDTHc; e12 = (g+8 < Gv) ? __expf(COEFFc*d*d) : 0.0f;
                d = rr1 - (g+9)*WIDTHc; e13 = (g+9 < Gv) ? __expf(COEFFc*d*d) : 0.0f;
                Af[s][0] = bf16pk(e00, e01);
                Af[s][1] = bf16pk(e10, e11);
                Af[s][2] = bf16pk(e02, e03);
                Af[s][3] = bf16pk(e12, e13);
            }

            #pragma unroll
            for (int s2 = 0; s2 < 8; ++s2) {
                #pragma unroll
                for (int nn = 0; nn < 2; ++nn) {
                    const int n = 2*s2 + nn;
                    float acc[4] = {0.0f, 0.0f, 0.0f, 0.0f};
                    mma_bf16(acc, Af[0], b1f[0][n]);
                    mma_bf16(acc, Af[1], b1f[1][n]);
                    float2 b12 = *(const float2*)(FB1 + 8*n + 2*qc);
                    A2[Mt][s2][2*nn    ] = ssp2(acc[0] + b12.x, acc[1] + b12.y, Mv0, ML0);
                    A2[Mt][s2][2*nn + 1] = ssp2(acc[2] + b12.x, acc[3] + b12.y, Mv1, ML1);
                }
            }
        }

        // ---- C: YT ready (warp-local rows only) ----
        asm volatile("cp.async.wait_group 0;" ::: "memory");
        __syncwarp();

        float* VSM = VSMB + par * 512;

        // ---- D/E: GEMM2 (K=128) + epilogue with analytic fb2 ----
        #pragma unroll
        for (int ch = 0; ch < 4; ++ch) {
            float acc2[2][4][4];
            #pragma unroll
            for (int Mt = 0; Mt < 2; ++Mt)
                #pragma unroll
                for (int n = 0; n < 4; ++n)
                    #pragma unroll
                    for (int i = 0; i < 4; ++i) acc2[Mt][n][i] = 0.0f;

            #pragma unroll
            for (int s = 0; s < 8; ++s) {
                #pragma unroll
                for (int n = 0; n < 4; ++n) {
                    int fB = 32*ch + 8*n + qr;
                    uint2 bb = *(const uint2*)(FW2T + fB*144 + s*16 + qc*4);
                    mma_bf16(acc2[0][n], A2[0][s], (const uint32_t*)&bb);
                    mma_bf16(acc2[1][n], A2[1][s], (const uint32_t*)&bb);
                }
            }

            float vp[8];
            #pragma unroll
            for (int i = 0; i < 8; ++i) vp[i] = 0.0f;
            #pragma unroll
            for (int Mt = 0; Mt < 2; ++Mt) {
                const int rl = 32*w + 16*Mt + qr;
                const float m0 = mk[Mt][0], m1 = mk[Mt][1];
                #pragma unroll
                for (int n = 0; n < 4; ++n) {
                    int fc = 32*ch + 8*n + 2*qc;
                    uint32_t y0 = *(const uint32_t*)(YT + rl*136 + fc);
                    uint32_t y1 = *(const uint32_t*)(YT + (rl+8)*136 + fc);
                    float2 f0 = bf2f(y0);
                    float2 f1 = bf2f(y1);
                    float2 fb = *(const float2*)(FB2 + fc);
                    float t0 = fmaf(m1, f1.x, m0*f0.x);
                    float t1 = fmaf(m1, f1.y, m0*f0.y);
                    vp[2*n]   = fmaf(acc2[Mt][n][0], f0.x,
                                fmaf(acc2[Mt][n][2], f1.x,
                                fmaf(fb.x, t0, vp[2*n])));
                    vp[2*n+1] = fmaf(acc2[Mt][n][1], f0.y,
                                fmaf(acc2[Mt][n][3], f1.y,
                                fmaf(fb.y, t1, vp[2*n+1])));
                }
            }
            #pragma unroll
            for (int i = 0; i < 8; ++i) {
                vp[i] += __shfl_xor_sync(0xffffffffu, vp[i], 4);
                vp[i] += __shfl_xor_sync(0xffffffffu, vp[i], 8);
                vp[i] += __shfl_xor_sync(0xffffffffu, vp[i], 16);
            }
            if (lane < 4) {
                #pragma unroll
                for (int n = 0; n < 4; ++n) {
                    VSM[w*128 + 32*ch + 8*n + 2*lane    ] = vp[2*n];
                    VSM[w*128 + 32*ch + 8*n + 2*lane + 1] = vp[2*n+1];
                }
            }
        }

        // ---- F: single barrier; G: cross-warp combine -> g_v ----
        __syncthreads();
        #pragma unroll
        for (int a = 0; a < 2; ++a)
            g_v[(size_t)(2*bt + a)*Fv + t] =
                VSM[(2*a)*128 + t] + VSM[(2*a+1)*128 + t];
        par ^= 1;
    }
}

// ---------------- kernel 3: x += dense(ssp(f2out(v)))  [+ next-layer in2f] ----------------
template<int DO_Y>
__global__ __launch_bounds__(256)
void fused_post(const float* __restrict__ W1, const float* __restrict__ B1,
                const float* __restrict__ W2, const float* __restrict__ B2,
                const float* __restrict__ W3, float* __restrict__ x)
{
    extern __shared__ float fsm[];
    float* bufA = fsm;              // [32][128]
    float* bufB = fsm + 32*Fv;      // [32][128]
    const int t = threadIdx.x;
    const int f = t & 127, q = t >> 7;
    const int row0 = blockIdx.x * 32;
    const int r0 = q * 16;

    {   // load v tile
        const float4* src = (const float4*)(g_v + (size_t)row0 * Fv);
        float4* dst = (float4*)bufA;
        #pragma unroll
        for (int i = 0; i < 4; ++i) dst[t + 256*i] = src[t + 256*i];
    }
    __syncthreads();

    float out[16];
    gemm_block<16>(bufA, W1, f, r0, out);
    {
        float b = __ldg(B1 + f);
        #pragma unroll
        for (int r = 0; r < 16; ++r)
            bufB[(r0 + r)*Fv + f] = ssp(out[r] + b);
    }
    __syncthreads();

    gemm_block<16>(bufB, W2, f, r0, out);
    {
        float b = __ldg(B2 + f);
        #pragma unroll
        for (int r = 0; r < 16; ++r) {
            size_t gi = (size_t)(row0 + r0 + r)*Fv + f;
            float xn = x[gi] + out[r] + b;
            x[gi] = xn;
            if (DO_Y) bufA[(r0 + r)*Fv + f] = xn;
        }
    }
    if (DO_Y) {
        __syncthreads();
        gemm_block<16>(bufA, W3, f, r0, out);
        #pragma unroll
        for (int r = 0; r < 16; ++r)
            g_y[(size_t)(row0 + r0 + r)*Fv + f] = __float2bfloat16(out[r]);
    }
}

// ---------------- launcher ----------------
extern "C" void kernel_launch(void* const* d_in, const int* in_sizes, int n_in,
                              void* d_out, int out_size)
{
    const int*   zA   = (const int*)  d_in[0];
    const float* pos  = (const float*)d_in[1];
    const float* cell = (const float*)d_in[2];
    const float* off  = (const float*)d_in[3];
    const int*   nbr  = (const int*)  d_in[4];
    const float* msk  = (const float*)d_in[5];
    const float* emb  = (const float*)d_in[6];
    const float* fw1  = (const float*)d_in[7];
    const float* fb1  = (const float*)d_in[8];
    const float* fw2  = (const float*)d_in[9];
    const float* fb2  = (const float*)d_in[10];
    const float* i2f  = (const float*)d_in[11];
    const float* f2o  = (const float*)d_in[12];
    const float* f2ob = (const float*)d_in[13];
    const float* dw   = (const float*)d_in[14];
    const float* db   = (const float*)d_in[15];
    float* x = (float*)d_out;

    cudaFuncSetAttribute(edge_mma_kernel,
                         cudaFuncAttributeMaxDynamicSharedMemorySize, SMEM_EDGE);
    cudaFuncSetAttribute(fused_post<1>,
                         cudaFuncAttributeMaxDynamicSharedMemorySize, 32768);
    cudaFuncSetAttribute(fused_post<0>,
                         cudaFuncAttributeMaxDynamicSharedMemorySize, 32768);

    init_y_kernel<<<(Bv*Av)/64, 256>>>(zA, pos, cell, off, nbr, emb, i2f, x);
    for (int l = 0; l < Lv; ++l) {
        edge_mma_kernel<<<EDGE_GRID, 128, SMEM_EDGE>>>(
            fw1 + (size_t)l*Gv*Fv, fb1 + (size_t)l*Fv,
            fw2 + (size_t)l*Fv*Fv, fb2 + (size_t)l*Fv, nbr, msk);
        if (l < Lv - 1)
            fused_post<1><<<(Bv*Av)/32, 256, 32768>>>(
                f2o + (size_t)l*Fv*Fv, f2ob + (size_t)l*Fv,
                dw  + (size_t)l*Fv*Fv, db   + (size_t)l*Fv,
                i2f + (size_t)(l+1)*Fv*Fv, x);
        else
            fused_post<0><<<(Bv*Av)/32, 256, 32768>>>(
                f2o + (size_t)l*Fv*Fv, f2ob + (size_t)l*Fv,
                dw  + (size_t)l*Fv*Fv, db   + (size_t)l*Fv,
                (const float*)nullptr, x);
    }
}